// round 3
// baseline (speedup 1.0000x reference)
#include <cuda_runtime.h>
#include <cstdint>
#include <cstddef>

#define NMAX 50048
#define EMAX 1700000
#define FDIM 128
#define GNUM 64
#define HID2 64
#define OUTD 10

// ---------------- scratch ----------------
__device__ __align__(16) float g_hw [NMAX * FDIM];
__device__ __align__(16) float g_acc[NMAX * FDIM];
__device__ __align__(16) float g_hsm[NMAX * FDIM];
__device__ __align__(16) float g_als[NMAX * 4];
__device__ __align__(16) float g_ald[NMAX * 4];
__device__ __align__(16) float g_colsum[GNUM * FDIM];
__device__ __align__(16) float g_num[GNUM * FDIM];
__device__ __align__(16) float g_gatesum[GNUM];
__device__ __align__(16) float g_hg [GNUM * FDIM];
__device__ int g_deg[NMAX];
__device__ int g_off[NMAX + 1];
__device__ int g_cur[NMAX];
__device__ int g_csr[EMAX];
__device__ int g_bsum[64];
__device__ int g_idx64;

__device__ __forceinline__ int load_idx(const void* p, long long i, int f64) {
    return f64 ? (int)((const long long*)p)[i] : ((const int*)p)[i];
}
__device__ __forceinline__ void red_add_v4(float* ptr, float a, float b, float c, float d) {
    asm volatile("red.global.add.v4.f32 [%0], {%1,%2,%3,%4};"
                 :: "l"(ptr), "f"(a), "f"(b), "f"(c), "f"(d) : "memory");
}

__global__ void k_probe(const void* ei) {
    if (threadIdx.x == 0) {
        const int* w = (const int*)ei;
        int f = 1;
        for (int i = 0; i < 64; i++) if (w[2 * i + 1] != 0) { f = 0; break; }
        g_idx64 = f;
    }
}

__global__ void k_zero_pre(int N) {
    int t = blockIdx.x * blockDim.x + threadIdx.x;
    if (t < N) g_deg[t] = 0;
    if (t < GNUM * FDIM) { g_colsum[t] = 0.f; g_num[t] = 0.f; g_hg[t] = 0.f; }
    if (t < GNUM) g_gatesum[t] = 0.f;
}

__global__ void k_hist(const void* __restrict__ ei, long long E) {
    long long t = (long long)blockIdx.x * blockDim.x + threadIdx.x;
    if (t >= E) return;
    int d = load_idx(ei, E + t, g_idx64);
    atomicAdd(&g_deg[d], 1);
}

// ---- multi-block exclusive scan: local scan + block sums ----
__global__ void k_scan1(int N) {
    __shared__ int wsum[32];
    int b = blockIdx.x;
    int i = b * 1024 + threadIdx.x;
    int lane = threadIdx.x & 31, w = threadIdx.x >> 5;
    int v = (i < N) ? g_deg[i] : 0;
    int x = v;
#pragma unroll
    for (int off = 1; off < 32; off <<= 1) {
        int y = __shfl_up_sync(0xffffffffu, x, off);
        if (lane >= off) x += y;
    }
    if (lane == 31) wsum[w] = x;
    __syncthreads();
    if (w == 0) {
        int s = wsum[lane];
#pragma unroll
        for (int off = 1; off < 32; off <<= 1) {
            int y = __shfl_up_sync(0xffffffffu, s, off);
            if (lane >= off) s += y;
        }
        wsum[lane] = s;
    }
    __syncthreads();
    int excl = x - v + (w ? wsum[w - 1] : 0);
    if (i < N) g_off[i] = excl;
    if (threadIdx.x == 1023) g_bsum[b] = excl + v;
}

__global__ void k_scan2(int nb, int N) {
    if (threadIdx.x == 0) {
        int run = 0;
        for (int b = 0; b < nb; b++) { int t = g_bsum[b]; g_bsum[b] = run; run += t; }
        g_off[N] = run;
    }
}

__global__ void k_scan3(int N) {
    int i = blockIdx.x * 1024 + threadIdx.x;
    if (i < N) {
        int o = g_off[i] + g_bsum[blockIdx.x];
        g_off[i] = o;
        g_cur[i] = o;
    }
}

__global__ void k_fill(const void* __restrict__ ei, long long E) {
    long long t = (long long)blockIdx.x * blockDim.x + threadIdx.x;
    if (t >= E) return;
    int f64 = g_idx64;
    int s = load_idx(ei, t, f64);
    int d = load_idx(ei, E + t, f64);
    int pos = atomicAdd(&g_cur[d], 1);
    g_csr[pos] = s;
}

// ---------------- GEMM: g_hw = A[N,128] @ W[128,128] ----------------
__global__ void k_gemm(const float* __restrict__ Ain, const float* __restrict__ W, int N) {
    const float* A = Ain ? Ain : g_hsm;
    __shared__ __align__(16) float sx[16 * 128];
    int row0 = blockIdx.x * 16;
    float4* sx4 = (float4*)sx;
    const float4* A4 = (const float4*)A;
    for (int i = threadIdx.x; i < 512; i += 128) {
        int r = i >> 5;
        if (row0 + r < N) sx4[i] = A4[(size_t)(row0 + r) * 32 + (i & 31)];
        else sx4[i] = make_float4(0.f, 0.f, 0.f, 0.f);
    }
    __syncthreads();
    int col = threadIdx.x;
    float acc[16];
#pragma unroll
    for (int r = 0; r < 16; r++) acc[r] = 0.f;
#pragma unroll 4
    for (int k = 0; k < 128; k++) {
        float w = W[k * 128 + col];
#pragma unroll
        for (int r = 0; r < 16; r++) acc[r] += sx[r * 128 + k] * w;
    }
#pragma unroll
    for (int r = 0; r < 16; r++) {
        int row = row0 + r;
        if (row < N) g_hw[(size_t)row * 128 + col] = acc[r];
    }
}

// ---------------- per-node attention logit pieces ----------------
__global__ void k_node_prep(const float* __restrict__ a_src, const float* __restrict__ a_dst, int N) {
    int t = blockIdx.x * blockDim.x + threadIdx.x;
    int n = t >> 5, lane = t & 31;
    if (n >= N) return;
    int h = lane >> 3;
    float4 v = ((const float4*)(g_hw + (size_t)n * 128))[lane];
    float4 a = ((const float4*)a_src)[lane];
    float4 b = ((const float4*)a_dst)[lane];
    float ps = v.x * a.x + v.y * a.y + v.z * a.z + v.w * a.w;
    float pd = v.x * b.x + v.y * b.y + v.z * b.z + v.w * b.w;
#pragma unroll
    for (int off = 4; off; off >>= 1) {
        ps += __shfl_xor_sync(0xffffffffu, ps, off);
        pd += __shfl_xor_sync(0xffffffffu, pd, off);
    }
    if ((lane & 7) == 0) {
        g_als[n * 4 + h] = ps;
        g_ald[n * 4 + h] = pd;
    }
}

// ---------------- aggregation: warp per dst (CSR gather) ----------------
__global__ void k_agg(const float* __restrict__ bvec, const void* __restrict__ batch, int N) {
    int n = blockIdx.x * 8 + (threadIdx.x >> 5);
    int lane = threadIdx.x & 31;
    if (n >= N) return;
    const unsigned FULL = 0xffffffffu;
    int hf = lane >> 3;
    int hq = lane & 3;
    float ald_q = g_ald[n * 4 + hq];
    float lg = g_als[n * 4 + hq] + ald_q;
    lg = lg > 0.f ? lg : 0.2f * lg;
    float wq = __expf(lg);
    float ssum_q = wq;
    float wf = __shfl_sync(FULL, wq, hf);
    float4 v = ((const float4*)(g_hw + (size_t)n * 128))[lane];
    float4 acc = make_float4(wf * v.x, wf * v.y, wf * v.z, wf * v.w);

    int beg = g_off[n], end = g_off[n + 1];
    for (int j = beg; j < end; j += 8) {
        int rem = end - j;
        int et = lane >> 2;
        int s_e = 0; float wv = 0.f;
        if (et < rem) {
            s_e = g_csr[j + et];
            float l2 = g_als[s_e * 4 + hq] + ald_q;
            l2 = l2 > 0.f ? l2 : 0.2f * l2;
            wv = __expf(l2);
        }
        ssum_q += wv;
        int cnt = rem < 8 ? rem : 8;
#pragma unroll
        for (int t = 0; t < 8; t++) {
            if (t >= cnt) break;
            float w = __shfl_sync(FULL, wv, t * 4 + hf);
            int s = __shfl_sync(FULL, s_e, t * 4);
            float4 u = ((const float4*)(g_hw + (size_t)s * 128))[lane];
            acc.x += w * u.x; acc.y += w * u.y; acc.z += w * u.z; acc.w += w * u.w;
        }
    }
#pragma unroll
    for (int off = 4; off < 32; off <<= 1) ssum_q += __shfl_xor_sync(FULL, ssum_q, off);
    float inv = __fdividef(1.f, __shfl_sync(FULL, ssum_q, hf));

    float4 b = ((const float4*)bvec)[lane];
    float4 u;
    u.x = fmaxf(acc.x * inv + b.x, 0.f);
    u.y = fmaxf(acc.y * inv + b.y, 0.f);
    u.z = fmaxf(acc.z * inv + b.z, 0.f);
    u.w = fmaxf(acc.w * inv + b.w, 0.f);
    float4 ev = make_float4(__expf(u.x), __expf(u.y), __expf(u.z), __expf(u.w));
    ((float4*)(g_acc + (size_t)n * 128))[lane] = ev;
    int g = load_idx(batch, n, g_idx64);
    red_add_v4(g_colsum + g * 128 + lane * 4, ev.x, ev.y, ev.z, ev.w);
}

// ---------------- column softmax + gate + weighted pool accumulation ----------
__global__ void k_ngp(const void* __restrict__ batch, const float* __restrict__ gate_w,
                      const float* __restrict__ gate_b, int N) {
    int t = blockIdx.x * blockDim.x + threadIdx.x;
    int n = t >> 5, lane = t & 31;
    if (n >= N) return;
    const unsigned FULL = 0xffffffffu;
    int g = load_idx(batch, n, g_idx64);
    float4 e = ((const float4*)(g_acc + (size_t)n * 128))[lane];
    float4 c = ((const float4*)(g_colsum + g * 128))[lane];
    float4 hs = make_float4(__fdividef(e.x, c.x), __fdividef(e.y, c.y),
                            __fdividef(e.z, c.z), __fdividef(e.w, c.w));
    ((float4*)(g_hsm + (size_t)n * 128))[lane] = hs;
    float4 gw = ((const float4*)gate_w)[lane];
    float p = hs.x * gw.x + hs.y * gw.y + hs.z * gw.z + hs.w * gw.w;
#pragma unroll
    for (int off = 16; off; off >>= 1) p += __shfl_xor_sync(FULL, p, off);
    float ge = __expf(p + gate_b[0]);
    red_add_v4(g_num + g * 128 + lane * 4, ge * hs.x, ge * hs.y, ge * hs.z, ge * hs.w);
    if (lane == 0) atomicAdd(&g_gatesum[g], ge);
}

// finalize pooled vector and zero per-layer accumulators for the next layer
__global__ void k_fin() {
    int t = blockIdx.x * blockDim.x + threadIdx.x;
    if (t < GNUM * FDIM) {
        g_hg[t] += g_num[t] * __fdividef(1.f, g_gatesum[t >> 7]);
        g_num[t] = 0.f;
        g_colsum[t] = 0.f;
    }
    if (t < GNUM) g_gatesum[t] = 0.f;
}

// ---------------- MLP head ----------------
__global__ void k_head(const float* __restrict__ lin_w, const float* __restrict__ lin_b,
                       const float* __restrict__ cls_w, const float* __restrict__ cls_b,
                       float* __restrict__ out) {
    int g = blockIdx.x;
    int j = threadIdx.x;
    __shared__ float sh[HID2];
    float a = lin_b[j];
#pragma unroll 4
    for (int k = 0; k < 128; k++) a += g_hg[g * 128 + k] * lin_w[k * HID2 + j];
    sh[j] = fmaxf(a, 0.f);
    __syncthreads();
    if (j < OUTD) {
        float o = cls_b[j];
#pragma unroll
        for (int k = 0; k < HID2; k++) o += sh[k] * cls_w[k * OUTD + j];
        out[g * OUTD + j] = o;
    }
}

// ---------------- launch ----------------
extern "C" void kernel_launch(void* const* d_in, const int* in_sizes, int n_in,
                              void* d_out, int out_size) {
    const float* x      = (const float*)d_in[0];
    const void*  ei     = d_in[1];
    const void*  batch  = d_in[2];
    const float* W1     = (const float*)d_in[3];
    const float* as1    = (const float*)d_in[4];
    const float* ad1    = (const float*)d_in[5];
    const float* b1     = (const float*)d_in[6];
    const float* W2     = (const float*)d_in[7];
    const float* as2    = (const float*)d_in[8];
    const float* ad2    = (const float*)d_in[9];
    const float* b2     = (const float*)d_in[10];
    const float* gate_w = (const float*)d_in[11];
    const float* gate_b = (const float*)d_in[12];
    const float* lin_w  = (const float*)d_in[13];
    const float* lin_b  = (const float*)d_in[14];
    const float* cls_w  = (const float*)d_in[15];
    const float* cls_b  = (const float*)d_in[16];
    float* out = (float*)d_out;

    int N = in_sizes[0] / FDIM;
    long long E = (long long)in_sizes[1] / 2;

    int nodeBlocks = (N + 7) / 8;
    int edgeBlocks = (int)((E + 255) / 256);
    int scanBlocks = (N + 1023) / 1024;
    int zgrid = (N > GNUM * FDIM ? N : GNUM * FDIM);

    k_probe<<<1, 32>>>(ei);
    k_zero_pre<<<(zgrid + 255) / 256, 256>>>(N);
    k_hist<<<edgeBlocks, 256>>>(ei, E);
    k_scan1<<<scanBlocks, 1024>>>(N);
    k_scan2<<<1, 32>>>(scanBlocks, N);
    k_scan3<<<scanBlocks, 1024>>>(N);
    k_fill<<<edgeBlocks, 256>>>(ei, E);

    // ---- layer 1 ----
    k_gemm<<<(N + 15) / 16, 128>>>(x, W1, N);
    k_node_prep<<<nodeBlocks, 256>>>(as1, ad1, N);
    k_agg<<<nodeBlocks, 256>>>(b1, batch, N);
    k_ngp<<<nodeBlocks, 256>>>(batch, gate_w, gate_b, N);
    k_fin<<<(GNUM * FDIM + 255) / 256, 256>>>();

    // ---- layer 2 ----
    k_gemm<<<(N + 15) / 16, 128>>>(nullptr, W2, N);
    k_node_prep<<<nodeBlocks, 256>>>(as2, ad2, N);
    k_agg<<<nodeBlocks, 256>>>(b2, batch, N);
    k_ngp<<<nodeBlocks, 256>>>(batch, gate_w, gate_b, N);
    k_fin<<<(GNUM * FDIM + 255) / 256, 256>>>();

    k_head<<<GNUM, HID2>>>(lin_w, lin_b, cls_w, cls_b, out);
}

// round 4
// speedup vs baseline: 1.4299x; 1.4299x over previous
#include <cuda_runtime.h>
#include <cuda_fp16.h>
#include <cstdint>
#include <cstddef>

#define NMAX 50048
#define EMAX 1700000
#define FDIM 128
#define GNUM 64
#define HID2 64
#define OUTD 10

// ---------------- scratch ----------------
__device__ __align__(16) unsigned short g_hw16[NMAX * FDIM];  // h rows in fp16
__device__ __align__(16) float g_acc[NMAX * FDIM];
__device__ __align__(16) float g_hsm[NMAX * FDIM];
__device__ __align__(16) float g_als[NMAX * 4];
__device__ __align__(16) float g_ald[NMAX * 4];
__device__ __align__(16) float g_colsum[GNUM * FDIM];
__device__ __align__(16) float g_num[GNUM * FDIM];
__device__ __align__(16) float g_gatesum[GNUM];
__device__ __align__(16) float g_hg [GNUM * FDIM];
__device__ int g_deg[NMAX];
__device__ int g_off[NMAX + 1];
__device__ int g_cur[NMAX];
__device__ int g_csr[EMAX];
__device__ int g_bsum[64];
__device__ int g_idx64;

__device__ __forceinline__ int load_idx(const void* p, long long i, int f64) {
    return f64 ? (int)((const long long*)p)[i] : ((const int*)p)[i];
}
__device__ __forceinline__ void red_add_v4(float* ptr, float a, float b, float c, float d) {
    asm volatile("red.global.add.v4.f32 [%0], {%1,%2,%3,%4};"
                 :: "l"(ptr), "f"(a), "f"(b), "f"(c), "f"(d) : "memory");
}
// load 4 features (fp16) -> float4
__device__ __forceinline__ float4 ldrow4h(const unsigned short* base, int lane) {
    uint2 raw = ((const uint2*)base)[lane];
    __half2 h01 = *reinterpret_cast<__half2*>(&raw.x);
    __half2 h23 = *reinterpret_cast<__half2*>(&raw.y);
    float2 f01 = __half22float2(h01);
    float2 f23 = __half22float2(h23);
    return make_float4(f01.x, f01.y, f23.x, f23.y);
}

__global__ void k_probe(const void* ei) {
    if (threadIdx.x == 0) {
        const int* w = (const int*)ei;
        int f = 1;
        for (int i = 0; i < 64; i++) if (w[2 * i + 1] != 0) { f = 0; break; }
        g_idx64 = f;
    }
}

__global__ void k_zero_pre(int N) {
    int t = blockIdx.x * blockDim.x + threadIdx.x;
    if (t < N) g_deg[t] = 0;
    if (t < GNUM * FDIM) { g_colsum[t] = 0.f; g_num[t] = 0.f; g_hg[t] = 0.f; }
    if (t < GNUM) g_gatesum[t] = 0.f;
}

__global__ void k_hist(const void* __restrict__ ei, long long E) {
    long long t = (long long)blockIdx.x * blockDim.x + threadIdx.x;
    if (t >= E) return;
    int d = load_idx(ei, E + t, g_idx64);
    atomicAdd(&g_deg[d], 1);
}

// ---- multi-block exclusive scan ----
__global__ void k_scan1(int N) {
    __shared__ int wsum[32];
    int b = blockIdx.x;
    int i = b * 1024 + threadIdx.x;
    int lane = threadIdx.x & 31, w = threadIdx.x >> 5;
    int v = (i < N) ? g_deg[i] : 0;
    int x = v;
#pragma unroll
    for (int off = 1; off < 32; off <<= 1) {
        int y = __shfl_up_sync(0xffffffffu, x, off);
        if (lane >= off) x += y;
    }
    if (lane == 31) wsum[w] = x;
    __syncthreads();
    if (w == 0) {
        int s = wsum[lane];
#pragma unroll
        for (int off = 1; off < 32; off <<= 1) {
            int y = __shfl_up_sync(0xffffffffu, s, off);
            if (lane >= off) s += y;
        }
        wsum[lane] = s;
    }
    __syncthreads();
    int excl = x - v + (w ? wsum[w - 1] : 0);
    if (i < N) g_off[i] = excl;
    if (threadIdx.x == 1023) g_bsum[b] = excl + v;
}

__global__ void k_scan2(int nb, int N) {
    if (threadIdx.x == 0) {
        int run = 0;
        for (int b = 0; b < nb; b++) { int t = g_bsum[b]; g_bsum[b] = run; run += t; }
        g_off[N] = run;
    }
}

__global__ void k_scan3(int N) {
    int i = blockIdx.x * 1024 + threadIdx.x;
    if (i < N) {
        int o = g_off[i] + g_bsum[blockIdx.x];
        g_off[i] = o;
        g_cur[i] = o;
    }
}

__global__ void k_fill(const void* __restrict__ ei, long long E) {
    long long t = (long long)blockIdx.x * blockDim.x + threadIdx.x;
    if (t >= E) return;
    int f64 = g_idx64;
    int s = load_idx(ei, t, f64);
    int d = load_idx(ei, E + t, f64);
    int pos = atomicAdd(&g_cur[d], 1);
    g_csr[pos] = s;
}

// ---------------- GEMM + fused node-prep ----------------
// g_hw16 = fp16(A @ W); g_als/g_ald = head-wise dots with a_src/a_dst.
__global__ void k_gemm(const float* __restrict__ Ain, const float* __restrict__ W,
                       const float* __restrict__ a_src, const float* __restrict__ a_dst, int N) {
    const float* A = Ain ? Ain : g_hsm;
    __shared__ __align__(16) float sx[16 * 128];
    int row0 = blockIdx.x * 16;
    float4* sx4 = (float4*)sx;
    const float4* A4 = (const float4*)A;
    for (int i = threadIdx.x; i < 512; i += 128) {
        int r = i >> 5;
        if (row0 + r < N) sx4[i] = A4[(size_t)(row0 + r) * 32 + (i & 31)];
        else sx4[i] = make_float4(0.f, 0.f, 0.f, 0.f);
    }
    __syncthreads();
    int col = threadIdx.x;
    float acc[16];
#pragma unroll
    for (int r = 0; r < 16; r++) acc[r] = 0.f;
#pragma unroll 4
    for (int k = 0; k < 128; k++) {
        float w = W[k * 128 + col];
#pragma unroll
        for (int r = 0; r < 16; r++) acc[r] += sx[r * 128 + k] * w;
    }
    float a_s = a_src[col];
    float a_d = a_dst[col];
    int wrp = threadIdx.x >> 5, lane = threadIdx.x & 31;
#pragma unroll
    for (int r = 0; r < 16; r++) {
        int row = row0 + r;
        float ps = acc[r] * a_s;
        float pd = acc[r] * a_d;
#pragma unroll
        for (int off = 16; off; off >>= 1) {
            ps += __shfl_xor_sync(0xffffffffu, ps, off);
            pd += __shfl_xor_sync(0xffffffffu, pd, off);
        }
        if (row < N) {
            g_hw16[(size_t)row * 128 + col] = __half_as_ushort(__float2half_rn(acc[r]));
            if (lane == 0) {
                g_als[row * 4 + wrp] = ps;
                g_ald[row * 4 + wrp] = pd;
            }
        }
    }
}

// ---------------- aggregation: warp per dst (CSR gather, fp16 rows) ----------
__global__ void k_agg(const float* __restrict__ bvec, const void* __restrict__ batch, int N) {
    int n = blockIdx.x * 8 + (threadIdx.x >> 5);
    int lane = threadIdx.x & 31;
    if (n >= N) return;
    const unsigned FULL = 0xffffffffu;
    int hf = lane >> 3;
    int hq = lane & 3;
    float ald_q = g_ald[n * 4 + hq];
    float lg = g_als[n * 4 + hq] + ald_q;
    lg = lg > 0.f ? lg : 0.2f * lg;
    float wq = __expf(lg);
    float ssum_q = wq;
    float wf = __shfl_sync(FULL, wq, hf);
    float4 v = ldrow4h(g_hw16 + (size_t)n * 128, lane);
    float4 acc = make_float4(wf * v.x, wf * v.y, wf * v.z, wf * v.w);

    int beg = g_off[n], end = g_off[n + 1];
    for (int j = beg; j < end; j += 8) {
        int rem = end - j;
        int et = lane >> 2;
        int s_e = 0; float wv = 0.f;
        if (et < rem) {
            s_e = g_csr[j + et];
            float l2 = g_als[s_e * 4 + hq] + ald_q;
            l2 = l2 > 0.f ? l2 : 0.2f * l2;
            wv = __expf(l2);
        }
        ssum_q += wv;
        int cnt = rem < 8 ? rem : 8;
#pragma unroll
        for (int t = 0; t < 8; t++) {
            if (t >= cnt) break;
            float w = __shfl_sync(FULL, wv, t * 4 + hf);
            int s = __shfl_sync(FULL, s_e, t * 4);
            float4 u = ldrow4h(g_hw16 + (size_t)s * 128, lane);
            acc.x += w * u.x; acc.y += w * u.y; acc.z += w * u.z; acc.w += w * u.w;
        }
    }
#pragma unroll
    for (int off = 4; off < 32; off <<= 1) ssum_q += __shfl_xor_sync(FULL, ssum_q, off);
    float inv = __fdividef(1.f, __shfl_sync(FULL, ssum_q, hf));

    float4 b = ((const float4*)bvec)[lane];
    float4 u;
    u.x = fmaxf(acc.x * inv + b.x, 0.f);
    u.y = fmaxf(acc.y * inv + b.y, 0.f);
    u.z = fmaxf(acc.z * inv + b.z, 0.f);
    u.w = fmaxf(acc.w * inv + b.w, 0.f);
    float4 ev = make_float4(__expf(u.x), __expf(u.y), __expf(u.z), __expf(u.w));
    ((float4*)(g_acc + (size_t)n * 128))[lane] = ev;
    int g = load_idx(batch, n, g_idx64);
    red_add_v4(g_colsum + g * 128 + lane * 4, ev.x, ev.y, ev.z, ev.w);
}

// ---------------- column softmax + gate + weighted pool accumulation ----------
__global__ void k_ngp(const void* __restrict__ batch, const float* __restrict__ gate_w,
                      const float* __restrict__ gate_b, int N) {
    int t = blockIdx.x * blockDim.x + threadIdx.x;
    int n = t >> 5, lane = t & 31;
    if (n >= N) return;
    const unsigned FULL = 0xffffffffu;
    int g = load_idx(batch, n, g_idx64);
    float4 e = ((const float4*)(g_acc + (size_t)n * 128))[lane];
    float4 c = ((const float4*)(g_colsum + g * 128))[lane];
    float4 hs = make_float4(__fdividef(e.x, c.x), __fdividef(e.y, c.y),
                            __fdividef(e.z, c.z), __fdividef(e.w, c.w));
    ((float4*)(g_hsm + (size_t)n * 128))[lane] = hs;
    float4 gw = ((const float4*)gate_w)[lane];
    float p = hs.x * gw.x + hs.y * gw.y + hs.z * gw.z + hs.w * gw.w;
#pragma unroll
    for (int off = 16; off; off >>= 1) p += __shfl_xor_sync(FULL, p, off);
    float ge = __expf(p + gate_b[0]);
    red_add_v4(g_num + g * 128 + lane * 4, ge * hs.x, ge * hs.y, ge * hs.z, ge * hs.w);
    if (lane == 0) atomicAdd(&g_gatesum[g], ge);
}

// finalize pooled vector and zero per-layer accumulators for the next layer
__global__ void k_fin() {
    int t = blockIdx.x * blockDim.x + threadIdx.x;
    if (t < GNUM * FDIM) {
        g_hg[t] += g_num[t] * __fdividef(1.f, g_gatesum[t >> 7]);
        g_num[t] = 0.f;
        g_colsum[t] = 0.f;
    }
    if (t < GNUM) g_gatesum[t] = 0.f;
}

// ---------------- MLP head ----------------
__global__ void k_head(const float* __restrict__ lin_w, const float* __restrict__ lin_b,
                       const float* __restrict__ cls_w, const float* __restrict__ cls_b,
                       float* __restrict__ out) {
    int g = blockIdx.x;
    int j = threadIdx.x;
    __shared__ float sh[HID2];
    float a = lin_b[j];
#pragma unroll 4
    for (int k = 0; k < 128; k++) a += g_hg[g * 128 + k] * lin_w[k * HID2 + j];
    sh[j] = fmaxf(a, 0.f);
    __syncthreads();
    if (j < OUTD) {
        float o = cls_b[j];
#pragma unroll
        for (int k = 0; k < HID2; k++) o += sh[k] * cls_w[k * OUTD + j];
        out[g * OUTD + j] = o;
    }
}

// ---------------- launch ----------------
extern "C" void kernel_launch(void* const* d_in, const int* in_sizes, int n_in,
                              void* d_out, int out_size) {
    const float* x      = (const float*)d_in[0];
    const void*  ei     = d_in[1];
    const void*  batch  = d_in[2];
    const float* W1     = (const float*)d_in[3];
    const float* as1    = (const float*)d_in[4];
    const float* ad1    = (const float*)d_in[5];
    const float* b1     = (const float*)d_in[6];
    const float* W2     = (const float*)d_in[7];
    const float* as2    = (const float*)d_in[8];
    const float* ad2    = (const float*)d_in[9];
    const float* b2     = (const float*)d_in[10];
    const float* gate_w = (const float*)d_in[11];
    const float* gate_b = (const float*)d_in[12];
    const float* lin_w  = (const float*)d_in[13];
    const float* lin_b  = (const float*)d_in[14];
    const float* cls_w  = (const float*)d_in[15];
    const float* cls_b  = (const float*)d_in[16];
    float* out = (float*)d_out;

    int N = in_sizes[0] / FDIM;
    long long E = (long long)in_sizes[1] / 2;

    int nodeBlocks = (N + 7) / 8;
    int edgeBlocks = (int)((E + 255) / 256);
    int scanBlocks = (N + 1023) / 1024;
    int zgrid = (N > GNUM * FDIM ? N : GNUM * FDIM);

    k_probe<<<1, 32>>>(ei);
    k_zero_pre<<<(zgrid + 255) / 256, 256>>>(N);
    k_hist<<<edgeBlocks, 256>>>(ei, E);
    k_scan1<<<scanBlocks, 1024>>>(N);
    k_scan2<<<1, 32>>>(scanBlocks, N);
    k_scan3<<<scanBlocks, 1024>>>(N);
    k_fill<<<edgeBlocks, 256>>>(ei, E);

    // ---- layer 1 ----
    k_gemm<<<(N + 15) / 16, 128>>>(x, W1, as1, ad1, N);
    k_agg<<<nodeBlocks, 256>>>(b1, batch, N);
    k_ngp<<<nodeBlocks, 256>>>(batch, gate_w, gate_b, N);
    k_fin<<<(GNUM * FDIM + 255) / 256, 256>>>();

    // ---- layer 2 ----
    k_gemm<<<(N + 15) / 16, 128>>>(nullptr, W2, as2, ad2, N);
    k_agg<<<nodeBlocks, 256>>>(b2, batch, N);
    k_ngp<<<nodeBlocks, 256>>>(batch, gate_w, gate_b, N);
    k_fin<<<(GNUM * FDIM + 255) / 256, 256>>>();

    k_head<<<GNUM, HID2>>>(lin_w, lin_b, cls_w, cls_b, out);
}

// round 5
// speedup vs baseline: 1.4726x; 1.0299x over previous
#include <cuda_runtime.h>
#include <cuda_fp16.h>
#include <cstdint>
#include <cstddef>

#define NMAX 50048
#define EMAX 1700000
#define FDIM 128
#define GNUM 64
#define HID2 64
#define OUTD 10

// ---------------- scratch ----------------
__device__ __align__(16) unsigned short g_hw16[NMAX * FDIM];
__device__ __align__(16) float g_acc[NMAX * FDIM];
__device__ __align__(16) float g_hsm[NMAX * FDIM];
__device__ __align__(16) float g_als[NMAX * 4];
__device__ __align__(16) float g_ald[NMAX * 4];
__device__ __align__(16) float g_colsum[GNUM * FDIM];
__device__ __align__(16) float g_num[GNUM * FDIM];
__device__ __align__(16) float g_gatesum[GNUM];
__device__ __align__(16) float g_hg [GNUM * FDIM];
__device__ int g_src32[EMAX];
__device__ int g_dst32[EMAX];
__device__ int g_deg[NMAX];
__device__ int g_off[NMAX + 1];
__device__ int g_cur[NMAX];
__device__ int g_csr[EMAX];
__device__ int g_bsum[64];
__device__ int g_idx64;

__device__ __forceinline__ int load_idx(const void* p, long long i, int f64) {
    return f64 ? (int)((const long long*)p)[i] : ((const int*)p)[i];
}
__device__ __forceinline__ void red_add_v4(float* ptr, float a, float b, float c, float d) {
    asm volatile("red.global.add.v4.f32 [%0], {%1,%2,%3,%4};"
                 :: "l"(ptr), "f"(a), "f"(b), "f"(c), "f"(d) : "memory");
}
__device__ __forceinline__ float4 ldrow4h(const unsigned short* base, int lane) {
    uint2 raw = ((const uint2*)base)[lane];
    __half2 h01 = *reinterpret_cast<__half2*>(&raw.x);
    __half2 h23 = *reinterpret_cast<__half2*>(&raw.y);
    float2 f01 = __half22float2(h01);
    float2 f23 = __half22float2(h23);
    return make_float4(f01.x, f01.y, f23.x, f23.y);
}

__global__ void k_probe(const void* ei) {
    if (threadIdx.x == 0) {
        const int* w = (const int*)ei;
        int f = 1;
        for (int i = 0; i < 64; i++) if (w[2 * i + 1] != 0) { f = 0; break; }
        g_idx64 = f;
    }
}

__global__ void k_zero_pre(int N) {
    int t = blockIdx.x * blockDim.x + threadIdx.x;
    if (t < N) g_deg[t] = 0;
    if (t < GNUM * FDIM) { g_colsum[t] = 0.f; g_num[t] = 0.f; g_hg[t] = 0.f; }
    if (t < GNUM) g_gatesum[t] = 0.f;
}

// read edge list once: convert to int32 + degree histogram
__global__ void k_prep(const void* __restrict__ ei, long long E) {
    long long t = (long long)blockIdx.x * blockDim.x + threadIdx.x;
    if (t >= E) return;
    int f64 = g_idx64;
    int s = load_idx(ei, t, f64);
    int d = load_idx(ei, E + t, f64);
    g_src32[t] = s;
    g_dst32[t] = d;
    atomicAdd(&g_deg[d], 1);
}

// ---- multi-block exclusive scan ----
__global__ void k_scan1(int N) {
    __shared__ int wsum[32];
    int b = blockIdx.x;
    int i = b * 1024 + threadIdx.x;
    int lane = threadIdx.x & 31, w = threadIdx.x >> 5;
    int v = (i < N) ? g_deg[i] : 0;
    int x = v;
#pragma unroll
    for (int off = 1; off < 32; off <<= 1) {
        int y = __shfl_up_sync(0xffffffffu, x, off);
        if (lane >= off) x += y;
    }
    if (lane == 31) wsum[w] = x;
    __syncthreads();
    if (w == 0) {
        int s = wsum[lane];
#pragma unroll
        for (int off = 1; off < 32; off <<= 1) {
            int y = __shfl_up_sync(0xffffffffu, s, off);
            if (lane >= off) s += y;
        }
        wsum[lane] = s;
    }
    __syncthreads();
    int excl = x - v + (w ? wsum[w - 1] : 0);
    if (i < N) g_off[i] = excl;
    if (threadIdx.x == 1023) g_bsum[b] = excl + v;
}

__global__ void k_scan2(int nb, int N) {
    if (threadIdx.x == 0) {
        int run = 0;
        for (int b = 0; b < nb; b++) { int t = g_bsum[b]; g_bsum[b] = run; run += t; }
        g_off[N] = run;
    }
}

__global__ void k_scan3(int N) {
    int i = blockIdx.x * 1024 + threadIdx.x;
    if (i < N) {
        int o = g_off[i] + g_bsum[blockIdx.x];
        g_off[i] = o;
        g_cur[i] = o;
    }
}

__global__ void k_fill(long long E) {
    long long t = (long long)blockIdx.x * blockDim.x + threadIdx.x;
    if (t >= E) return;
    int s = g_src32[t];
    int d = g_dst32[t];
    int pos = atomicAdd(&g_cur[d], 1);
    g_csr[pos] = s;
}

// ---------------- GEMM (fma.rn.f32x2 packed) + fused node-prep ----------------
__global__ void k_gemm(const float* __restrict__ Ain, const float* __restrict__ W,
                       const float* __restrict__ a_src, const float* __restrict__ a_dst, int N) {
    const float* A = Ain ? Ain : g_hsm;
    __shared__ __align__(16) float sx[16 * 128];
    int row0 = blockIdx.x * 16;
    float4* sx4 = (float4*)sx;
    const float4* A4 = (const float4*)A;
    for (int i = threadIdx.x; i < 512; i += 128) {
        int r = i >> 5;
        if (row0 + r < N) sx4[i] = A4[(size_t)(row0 + r) * 32 + (i & 31)];
        else sx4[i] = make_float4(0.f, 0.f, 0.f, 0.f);
    }
    __syncthreads();
    int col = threadIdx.x;
    unsigned long long acc2[16];
#pragma unroll
    for (int r = 0; r < 16; r++) acc2[r] = 0ull;
#pragma unroll 4
    for (int k = 0; k < 128; k += 4) {
        float w0 = W[(k + 0) * 128 + col];
        float w1 = W[(k + 1) * 128 + col];
        float w2 = W[(k + 2) * 128 + col];
        float w3 = W[(k + 3) * 128 + col];
        unsigned long long wp01, wp23;
        asm("mov.b64 %0,{%1,%2};" : "=l"(wp01) : "f"(w0), "f"(w1));
        asm("mov.b64 %0,{%1,%2};" : "=l"(wp23) : "f"(w2), "f"(w3));
#pragma unroll
        for (int r = 0; r < 16; r++) {
            ulonglong2 a = *(const ulonglong2*)&sx[r * 128 + k];
            asm("fma.rn.f32x2 %0,%1,%2,%0;" : "+l"(acc2[r]) : "l"(a.x), "l"(wp01));
            asm("fma.rn.f32x2 %0,%1,%2,%0;" : "+l"(acc2[r]) : "l"(a.y), "l"(wp23));
        }
    }
    float acc[16];
#pragma unroll
    for (int r = 0; r < 16; r++) {
        float lo, hi;
        asm("mov.b64 {%0,%1},%2;" : "=f"(lo), "=f"(hi) : "l"(acc2[r]));
        acc[r] = lo + hi;
    }
    float a_s = a_src[col];
    float a_d = a_dst[col];
    int wrp = threadIdx.x >> 5, lane = threadIdx.x & 31;
#pragma unroll
    for (int r = 0; r < 16; r++) {
        int row = row0 + r;
        float ps = acc[r] * a_s;
        float pd = acc[r] * a_d;
#pragma unroll
        for (int off = 16; off; off >>= 1) {
            ps += __shfl_xor_sync(0xffffffffu, ps, off);
            pd += __shfl_xor_sync(0xffffffffu, pd, off);
        }
        if (row < N) {
            g_hw16[(size_t)row * 128 + col] = __half_as_ushort(__float2half_rn(acc[r]));
            if (lane == 0) {
                g_als[row * 4 + wrp] = ps;
                g_ald[row * 4 + wrp] = pd;
            }
        }
    }
}

// ---------------- aggregation: warp per dst (CSR gather, fp16 rows) ----------
__global__ void k_agg(const float* __restrict__ bvec, const void* __restrict__ batch, int N) {
    int n = blockIdx.x * 8 + (threadIdx.x >> 5);
    int lane = threadIdx.x & 31;
    if (n >= N) return;
    const unsigned FULL = 0xffffffffu;
    int hf = lane >> 3;
    int hq = lane & 3;
    float ald_q = g_ald[n * 4 + hq];
    float lg = g_als[n * 4 + hq] + ald_q;
    lg = lg > 0.f ? lg : 0.2f * lg;
    float wq = __expf(lg);
    float ssum_q = wq;
    float wf = __shfl_sync(FULL, wq, hf);
    float4 v = ldrow4h(g_hw16 + (size_t)n * 128, lane);
    float4 acc = make_float4(wf * v.x, wf * v.y, wf * v.z, wf * v.w);

    int beg = g_off[n], end = g_off[n + 1];
    for (int j = beg; j < end; j += 8) {
        int rem = end - j;
        int et = lane >> 2;
        int s_e = 0; float wv = 0.f;
        if (et < rem) {
            s_e = g_csr[j + et];
            float l2 = g_als[s_e * 4 + hq] + ald_q;
            l2 = l2 > 0.f ? l2 : 0.2f * l2;
            wv = __expf(l2);
        }
        ssum_q += wv;
        int cnt = rem < 8 ? rem : 8;
#pragma unroll
        for (int t = 0; t < 8; t++) {
            if (t >= cnt) break;
            float w = __shfl_sync(FULL, wv, t * 4 + hf);
            int s = __shfl_sync(FULL, s_e, t * 4);
            float4 u = ldrow4h(g_hw16 + (size_t)s * 128, lane);
            acc.x += w * u.x; acc.y += w * u.y; acc.z += w * u.z; acc.w += w * u.w;
        }
    }
#pragma unroll
    for (int off = 4; off < 32; off <<= 1) ssum_q += __shfl_xor_sync(FULL, ssum_q, off);
    float inv = __fdividef(1.f, __shfl_sync(FULL, ssum_q, hf));

    float4 b = ((const float4*)bvec)[lane];
    float4 u;
    u.x = fmaxf(acc.x * inv + b.x, 0.f);
    u.y = fmaxf(acc.y * inv + b.y, 0.f);
    u.z = fmaxf(acc.z * inv + b.z, 0.f);
    u.w = fmaxf(acc.w * inv + b.w, 0.f);
    float4 ev = make_float4(__expf(u.x), __expf(u.y), __expf(u.z), __expf(u.w));
    ((float4*)(g_acc + (size_t)n * 128))[lane] = ev;
    int g = load_idx(batch, n, g_idx64);
    red_add_v4(g_colsum + g * 128 + lane * 4, ev.x, ev.y, ev.z, ev.w);
}

// ---------------- column softmax + gate + weighted pool accumulation ----------
__global__ void k_ngp(const void* __restrict__ batch, const float* __restrict__ gate_w,
                      const float* __restrict__ gate_b, int N) {
    int t = blockIdx.x * blockDim.x + threadIdx.x;
    int n = t >> 5, lane = t & 31;
    if (n >= N) return;
    const unsigned FULL = 0xffffffffu;
    int g = load_idx(batch, n, g_idx64);
    float4 e = ((const float4*)(g_acc + (size_t)n * 128))[lane];
    float4 c = ((const float4*)(g_colsum + g * 128))[lane];
    float4 hs = make_float4(__fdividef(e.x, c.x), __fdividef(e.y, c.y),
                            __fdividef(e.z, c.z), __fdividef(e.w, c.w));
    ((float4*)(g_hsm + (size_t)n * 128))[lane] = hs;
    float4 gw = ((const float4*)gate_w)[lane];
    float p = hs.x * gw.x + hs.y * gw.y + hs.z * gw.z + hs.w * gw.w;
#pragma unroll
    for (int off = 16; off; off >>= 1) p += __shfl_xor_sync(FULL, p, off);
    float ge = __expf(p + gate_b[0]);
    red_add_v4(g_num + g * 128 + lane * 4, ge * hs.x, ge * hs.y, ge * hs.z, ge * hs.w);
    if (lane == 0) atomicAdd(&g_gatesum[g], ge);
}

__global__ void k_fin() {
    int t = blockIdx.x * blockDim.x + threadIdx.x;
    if (t < GNUM * FDIM) {
        g_hg[t] += g_num[t] * __fdividef(1.f, g_gatesum[t >> 7]);
        g_num[t] = 0.f;
        g_colsum[t] = 0.f;
    }
    if (t < GNUM) g_gatesum[t] = 0.f;
}

// ---------------- MLP head ----------------
__global__ void k_head(const float* __restrict__ lin_w, const float* __restrict__ lin_b,
                       const float* __restrict__ cls_w, const float* __restrict__ cls_b,
                       float* __restrict__ out) {
    int g = blockIdx.x;
    int j = threadIdx.x;
    __shared__ float sh[HID2];
    float a = lin_b[j];
#pragma unroll 4
    for (int k = 0; k < 128; k++) a += g_hg[g * 128 + k] * lin_w[k * HID2 + j];
    sh[j] = fmaxf(a, 0.f);
    __syncthreads();
    if (j < OUTD) {
        float o = cls_b[j];
#pragma unroll
        for (int k = 0; k < HID2; k++) o += sh[k] * cls_w[k * OUTD + j];
        out[g * OUTD + j] = o;
    }
}

// ---------------- launch ----------------
extern "C" void kernel_launch(void* const* d_in, const int* in_sizes, int n_in,
                              void* d_out, int out_size) {
    const float* x      = (const float*)d_in[0];
    const void*  ei     = d_in[1];
    const void*  batch  = d_in[2];
    const float* W1     = (const float*)d_in[3];
    const float* as1    = (const float*)d_in[4];
    const float* ad1    = (const float*)d_in[5];
    const float* b1     = (const float*)d_in[6];
    const float* W2     = (const float*)d_in[7];
    const float* as2    = (const float*)d_in[8];
    const float* ad2    = (const float*)d_in[9];
    const float* b2     = (const float*)d_in[10];
    const float* gate_w = (const float*)d_in[11];
    const float* gate_b = (const float*)d_in[12];
    const float* lin_w  = (const float*)d_in[13];
    const float* lin_b  = (const float*)d_in[14];
    const float* cls_w  = (const float*)d_in[15];
    const float* cls_b  = (const float*)d_in[16];
    float* out = (float*)d_out;

    int N = in_sizes[0] / FDIM;
    long long E = (long long)in_sizes[1] / 2;

    int nodeBlocks = (N + 7) / 8;
    int edgeBlocks = (int)((E + 255) / 256);
    int scanBlocks = (N + 1023) / 1024;
    int zgrid = (N > GNUM * FDIM ? N : GNUM * FDIM);

    k_probe<<<1, 32>>>(ei);
    k_zero_pre<<<(zgrid + 255) / 256, 256>>>(N);
    k_prep<<<edgeBlocks, 256>>>(ei, E);
    k_scan1<<<scanBlocks, 1024>>>(N);
    k_scan2<<<1, 32>>>(scanBlocks, N);
    k_scan3<<<scanBlocks, 1024>>>(N);
    k_fill<<<edgeBlocks, 256>>>(E);

    // ---- layer 1 ----
    k_gemm<<<(N + 15) / 16, 128>>>(x, W1, as1, ad1, N);
    k_agg<<<nodeBlocks, 256>>>(b1, batch, N);
    k_ngp<<<nodeBlocks, 256>>>(batch, gate_w, gate_b, N);
    k_fin<<<(GNUM * FDIM + 255) / 256, 256>>>();

    // ---- layer 2 ----
    k_gemm<<<(N + 15) / 16, 128>>>(nullptr, W2, as2, ad2, N);
    k_agg<<<nodeBlocks, 256>>>(b2, batch, N);
    k_ngp<<<nodeBlocks, 256>>>(batch, gate_w, gate_b, N);
    k_fin<<<(GNUM * FDIM + 255) / 256, 256>>>();

    k_head<<<GNUM, HID2>>>(lin_w, lin_b, cls_w, cls_b, out);
}

// round 6
// speedup vs baseline: 1.5974x; 1.0847x over previous
#include <cuda_runtime.h>
#include <cuda_fp16.h>
#include <cstdint>
#include <cstddef>

#define NMAX 50048
#define EMAX 1700000
#define FDIM 128
#define GNUM 64
#define HID2 64
#define OUTD 10

// ---------------- scratch ----------------
__device__ __align__(16) unsigned short g_hw16[NMAX * FDIM];
__device__ __align__(16) float g_acc[NMAX * FDIM];
__device__ __align__(16) float g_als[NMAX * 4];
__device__ __align__(16) float g_ald[NMAX * 4];
__device__ __align__(16) float g_colsum[GNUM * FDIM];
__device__ __align__(16) float g_num[GNUM * FDIM];
__device__ __align__(16) float g_gatesum[GNUM];
__device__ __align__(16) float g_hg [GNUM * FDIM];
__device__ int g_src32[EMAX];
__device__ int g_dst32[EMAX];
__device__ int g_deg[NMAX];
__device__ int g_off[NMAX + 1];
__device__ int g_cur[NMAX];
__device__ int g_csr[EMAX];
__device__ int g_bsum[64];
__device__ int g_idx64;

__device__ __forceinline__ int load_idx(const void* p, long long i, int f64) {
    return f64 ? (int)((const long long*)p)[i] : ((const int*)p)[i];
}
__device__ __forceinline__ void red_add_v4(float* ptr, float a, float b, float c, float d) {
    asm volatile("red.global.add.v4.f32 [%0], {%1,%2,%3,%4};"
                 :: "l"(ptr), "f"(a), "f"(b), "f"(c), "f"(d) : "memory");
}
__device__ __forceinline__ float4 ldrow4h(const unsigned short* base, int lane) {
    uint2 raw = ((const uint2*)base)[lane];
    __half2 h01 = *reinterpret_cast<__half2*>(&raw.x);
    __half2 h23 = *reinterpret_cast<__half2*>(&raw.y);
    float2 f01 = __half22float2(h01);
    float2 f23 = __half22float2(h23);
    return make_float4(f01.x, f01.y, f23.x, f23.y);
}

__global__ void k_probe(const void* ei) {
    if (threadIdx.x == 0) {
        const int* w = (const int*)ei;
        int f = 1;
        for (int i = 0; i < 64; i++) if (w[2 * i + 1] != 0) { f = 0; break; }
        g_idx64 = f;
    }
}

__global__ void k_zero_pre(int N) {
    int t = blockIdx.x * blockDim.x + threadIdx.x;
    if (t < N) g_deg[t] = 0;
    if (t < GNUM * FDIM) { g_colsum[t] = 0.f; g_num[t] = 0.f; g_hg[t] = 0.f; }
    if (t < GNUM) g_gatesum[t] = 0.f;
}

__global__ void k_prep(const void* __restrict__ ei, long long E) {
    long long t = (long long)blockIdx.x * blockDim.x + threadIdx.x;
    if (t >= E) return;
    int f64 = g_idx64;
    int s = load_idx(ei, t, f64);
    int d = load_idx(ei, E + t, f64);
    g_src32[t] = s;
    g_dst32[t] = d;
    atomicAdd(&g_deg[d], 1);
}

// ---- multi-block exclusive scan ----
__global__ void k_scan1(int N) {
    __shared__ int wsum[32];
    int b = blockIdx.x;
    int i = b * 1024 + threadIdx.x;
    int lane = threadIdx.x & 31, w = threadIdx.x >> 5;
    int v = (i < N) ? g_deg[i] : 0;
    int x = v;
#pragma unroll
    for (int off = 1; off < 32; off <<= 1) {
        int y = __shfl_up_sync(0xffffffffu, x, off);
        if (lane >= off) x += y;
    }
    if (lane == 31) wsum[w] = x;
    __syncthreads();
    if (w == 0) {
        int s = wsum[lane];
#pragma unroll
        for (int off = 1; off < 32; off <<= 1) {
            int y = __shfl_up_sync(0xffffffffu, s, off);
            if (lane >= off) s += y;
        }
        wsum[lane] = s;
    }
    __syncthreads();
    int excl = x - v + (w ? wsum[w - 1] : 0);
    if (i < N) g_off[i] = excl;
    if (threadIdx.x == 1023) g_bsum[b] = excl + v;
}

__global__ void k_scan2(int nb, int N) {
    if (threadIdx.x == 0) {
        int run = 0;
        for (int b = 0; b < nb; b++) { int t = g_bsum[b]; g_bsum[b] = run; run += t; }
        g_off[N] = run;
    }
}

__global__ void k_scan3(int N) {
    int i = blockIdx.x * 1024 + threadIdx.x;
    if (i < N) {
        int o = g_off[i] + g_bsum[blockIdx.x];
        g_off[i] = o;
        g_cur[i] = o;
    }
}

__global__ void k_fill(long long E) {
    long long t = (long long)blockIdx.x * blockDim.x + threadIdx.x;
    if (t >= E) return;
    int s = g_src32[t];
    int d = g_dst32[t];
    int pos = atomicAdd(&g_cur[d], 1);
    g_csr[pos] = s;
}

// GEMM core on an smem tile: 16 rows x 128, f32x2 packed; writes hw16 + als/ald.
__device__ __forceinline__ void gemm_tile(const float* sx, const float* __restrict__ W,
                                          const float* __restrict__ a_src,
                                          const float* __restrict__ a_dst,
                                          int row0, int N) {
    int col = threadIdx.x;
    unsigned long long acc2[16];
#pragma unroll
    for (int r = 0; r < 16; r++) acc2[r] = 0ull;
#pragma unroll 4
    for (int k = 0; k < 128; k += 4) {
        float w0 = W[(k + 0) * 128 + col];
        float w1 = W[(k + 1) * 128 + col];
        float w2 = W[(k + 2) * 128 + col];
        float w3 = W[(k + 3) * 128 + col];
        unsigned long long wp01, wp23;
        asm("mov.b64 %0,{%1,%2};" : "=l"(wp01) : "f"(w0), "f"(w1));
        asm("mov.b64 %0,{%1,%2};" : "=l"(wp23) : "f"(w2), "f"(w3));
#pragma unroll
        for (int r = 0; r < 16; r++) {
            ulonglong2 a = *(const ulonglong2*)&sx[r * 128 + k];
            asm("fma.rn.f32x2 %0,%1,%2,%0;" : "+l"(acc2[r]) : "l"(a.x), "l"(wp01));
            asm("fma.rn.f32x2 %0,%1,%2,%0;" : "+l"(acc2[r]) : "l"(a.y), "l"(wp23));
        }
    }
    float a_s = a_src[col];
    float a_d = a_dst[col];
    int wrp = threadIdx.x >> 5, lane = threadIdx.x & 31;
#pragma unroll
    for (int r = 0; r < 16; r++) {
        float lo, hi;
        asm("mov.b64 {%0,%1},%2;" : "=f"(lo), "=f"(hi) : "l"(acc2[r]));
        float acc = lo + hi;
        int row = row0 + r;
        float ps = acc * a_s;
        float pd = acc * a_d;
#pragma unroll
        for (int off = 16; off; off >>= 1) {
            ps += __shfl_xor_sync(0xffffffffu, ps, off);
            pd += __shfl_xor_sync(0xffffffffu, pd, off);
        }
        if (row < N) {
            g_hw16[(size_t)row * 128 + col] = __half_as_ushort(__float2half_rn(acc));
            if (lane == 0) {
                g_als[row * 4 + wrp] = ps;
                g_ald[row * 4 + wrp] = pd;
            }
        }
    }
}

// ---------------- layer-1 GEMM (input x) ----------------
__global__ void k_gemm(const float* __restrict__ A, const float* __restrict__ W,
                       const float* __restrict__ a_src, const float* __restrict__ a_dst, int N) {
    __shared__ __align__(16) float sx[16 * 128];
    int row0 = blockIdx.x * 16;
    float4* sx4 = (float4*)sx;
    const float4* A4 = (const float4*)A;
    for (int i = threadIdx.x; i < 512; i += 128) {
        int r = i >> 5;
        if (row0 + r < N) sx4[i] = A4[(size_t)(row0 + r) * 32 + (i & 31)];
        else sx4[i] = make_float4(0.f, 0.f, 0.f, 0.f);
    }
    __syncthreads();
    gemm_tile(sx, W, a_src, a_dst, row0, N);
}

// ---------------- fused: layer-1 ngp (softmax+gate+pool) + layer-2 GEMM -------
__global__ void k_ngp_gemm(const void* __restrict__ batch,
                           const float* __restrict__ gate_w, const float* __restrict__ gate_b,
                           const float* __restrict__ W,
                           const float* __restrict__ a_src, const float* __restrict__ a_dst,
                           int N) {
    __shared__ __align__(16) float sx[16 * 128];
    __shared__ float sge[16];
    __shared__ int sgid[16];
    __shared__ float spart[16][4];
    int row0 = blockIdx.x * 16;
    int tid = threadIdx.x;
    int wrp = tid >> 5, lane = tid & 31;
    int f64 = g_idx64;
    float4* sx4 = (float4*)sx;
    const float4* acc4 = (const float4*)g_acc;
    // load exp values, divide by per-graph column sum -> hs into smem
    for (int i = tid; i < 512; i += 128) {
        int r = i >> 5, c = i & 31;
        int row = row0 + r;
        if (row < N) {
            int g = load_idx(batch, row, f64);
            if (c == 0) sgid[r] = g;
            float4 e = acc4[(size_t)row * 32 + c];
            float4 cs = ((const float4*)(g_colsum + g * 128))[c];
            sx4[i] = make_float4(__fdividef(e.x, cs.x), __fdividef(e.y, cs.y),
                                 __fdividef(e.z, cs.z), __fdividef(e.w, cs.w));
        } else {
            if (c == 0) sgid[r] = 0;
            sx4[i] = make_float4(0.f, 0.f, 0.f, 0.f);
        }
    }
    __syncthreads();
    // gate logits: per-row dot(hs, gate_w)
    float gwv = gate_w[tid];
#pragma unroll
    for (int r = 0; r < 16; r++) {
        float p = sx[r * 128 + tid] * gwv;
#pragma unroll
        for (int off = 16; off; off >>= 1) p += __shfl_xor_sync(0xffffffffu, p, off);
        if (lane == 0) spart[r][wrp] = p;
    }
    __syncthreads();
    if (tid < 16) {
        float p = spart[tid][0] + spart[tid][1] + spart[tid][2] + spart[tid][3] + gate_b[0];
        float ge = __expf(p);
        sge[tid] = ge;
        if (row0 + tid < N) atomicAdd(&g_gatesum[sgid[tid]], ge);
    }
    __syncthreads();
    // pooled numerator: warp w handles rows {w, w+4, w+8, w+12}
#pragma unroll
    for (int rr = 0; rr < 4; rr++) {
        int r = wrp + rr * 4;
        if (row0 + r < N) {
            float ge = sge[r];
            float4 hs = sx4[r * 32 + lane];
            red_add_v4(g_num + sgid[r] * 128 + lane * 4,
                       ge * hs.x, ge * hs.y, ge * hs.z, ge * hs.w);
        }
    }
    // layer-2 GEMM on the hs tile
    gemm_tile(sx, W, a_src, a_dst, row0, N);
}

// ---------------- aggregation: warp per dst (CSR gather, fp16 rows) ----------
__global__ void k_agg(const float* __restrict__ bvec, const void* __restrict__ batch, int N) {
    int n = blockIdx.x * 8 + (threadIdx.x >> 5);
    int lane = threadIdx.x & 31;
    if (n >= N) return;
    const unsigned FULL = 0xffffffffu;
    int hf = lane >> 3;
    int hq = lane & 3;
    float ald_q = g_ald[n * 4 + hq];
    float lg = g_als[n * 4 + hq] + ald_q;
    lg = lg > 0.f ? lg : 0.2f * lg;
    float wq = __expf(lg);
    float ssum_q = wq;
    float wf = __shfl_sync(FULL, wq, hf);
    float4 v = ldrow4h(g_hw16 + (size_t)n * 128, lane);
    float4 acc = make_float4(wf * v.x, wf * v.y, wf * v.z, wf * v.w);

    int beg = g_off[n], end = g_off[n + 1];
    for (int j = beg; j < end; j += 8) {
        int rem = end - j;
        int et = lane >> 2;
        int s_e = 0; float wv = 0.f;
        if (et < rem) {
            s_e = g_csr[j + et];
            float l2 = g_als[s_e * 4 + hq] + ald_q;
            l2 = l2 > 0.f ? l2 : 0.2f * l2;
            wv = __expf(l2);
        }
        ssum_q += wv;
        int cnt = rem < 8 ? rem : 8;
#pragma unroll
        for (int t = 0; t < 8; t++) {
            if (t >= cnt) break;
            float w = __shfl_sync(FULL, wv, t * 4 + hf);
            int s = __shfl_sync(FULL, s_e, t * 4);
            float4 u = ldrow4h(g_hw16 + (size_t)s * 128, lane);
            acc.x += w * u.x; acc.y += w * u.y; acc.z += w * u.z; acc.w += w * u.w;
        }
    }
#pragma unroll
    for (int off = 4; off < 32; off <<= 1) ssum_q += __shfl_xor_sync(FULL, ssum_q, off);
    float inv = __fdividef(1.f, __shfl_sync(FULL, ssum_q, hf));

    float4 b = ((const float4*)bvec)[lane];
    float4 u;
    u.x = fmaxf(acc.x * inv + b.x, 0.f);
    u.y = fmaxf(acc.y * inv + b.y, 0.f);
    u.z = fmaxf(acc.z * inv + b.z, 0.f);
    u.w = fmaxf(acc.w * inv + b.w, 0.f);
    float4 ev = make_float4(__expf(u.x), __expf(u.y), __expf(u.z), __expf(u.w));
    ((float4*)(g_acc + (size_t)n * 128))[lane] = ev;
    int g = load_idx(batch, n, g_idx64);
    red_add_v4(g_colsum + g * 128 + lane * 4, ev.x, ev.y, ev.z, ev.w);
}

// ---------------- layer-2 standalone: softmax + gate + pool (no hsm store) ----
__global__ void k_ngp(const void* __restrict__ batch, const float* __restrict__ gate_w,
                      const float* __restrict__ gate_b, int N) {
    int t = blockIdx.x * blockDim.x + threadIdx.x;
    int n = t >> 5, lane = t & 31;
    if (n >= N) return;
    const unsigned FULL = 0xffffffffu;
    int g = load_idx(batch, n, g_idx64);
    float4 e = ((const float4*)(g_acc + (size_t)n * 128))[lane];
    float4 c = ((const float4*)(g_colsum + g * 128))[lane];
    float4 hs = make_float4(__fdividef(e.x, c.x), __fdividef(e.y, c.y),
                            __fdividef(e.z, c.z), __fdividef(e.w, c.w));
    float4 gw = ((const float4*)gate_w)[lane];
    float p = hs.x * gw.x + hs.y * gw.y + hs.z * gw.z + hs.w * gw.w;
#pragma unroll
    for (int off = 16; off; off >>= 1) p += __shfl_xor_sync(FULL, p, off);
    float ge = __expf(p + gate_b[0]);
    red_add_v4(g_num + g * 128 + lane * 4, ge * hs.x, ge * hs.y, ge * hs.z, ge * hs.w);
    if (lane == 0) atomicAdd(&g_gatesum[g], ge);
}

__global__ void k_fin() {
    int t = blockIdx.x * blockDim.x + threadIdx.x;
    if (t < GNUM * FDIM) {
        g_hg[t] += g_num[t] * __fdividef(1.f, g_gatesum[t >> 7]);
        g_num[t] = 0.f;
        g_colsum[t] = 0.f;
    }
    if (t < GNUM) g_gatesum[t] = 0.f;
}

// ---------------- MLP head ----------------
__global__ void k_head(const float* __restrict__ lin_w, const float* __restrict__ lin_b,
                       const float* __restrict__ cls_w, const float* __restrict__ cls_b,
                       float* __restrict__ out) {
    int g = blockIdx.x;
    int j = threadIdx.x;
    __shared__ float sh[HID2];
    float a = lin_b[j];
#pragma unroll 4
    for (int k = 0; k < 128; k++) a += g_hg[g * 128 + k] * lin_w[k * HID2 + j];
    sh[j] = fmaxf(a, 0.f);
    __syncthreads();
    if (j < OUTD) {
        float o = cls_b[j];
#pragma unroll
        for (int k = 0; k < HID2; k++) o += sh[k] * cls_w[k * OUTD + j];
        out[g * OUTD + j] = o;
    }
}

// ---------------- launch ----------------
extern "C" void kernel_launch(void* const* d_in, const int* in_sizes, int n_in,
                              void* d_out, int out_size) {
    const float* x      = (const float*)d_in[0];
    const void*  ei     = d_in[1];
    const void*  batch  = d_in[2];
    const float* W1     = (const float*)d_in[3];
    const float* as1    = (const float*)d_in[4];
    const float* ad1    = (const float*)d_in[5];
    const float* b1     = (const float*)d_in[6];
    const float* W2     = (const float*)d_in[7];
    const float* as2    = (const float*)d_in[8];
    const float* ad2    = (const float*)d_in[9];
    const float* b2     = (const float*)d_in[10];
    const float* gate_w = (const float*)d_in[11];
    const float* gate_b = (const float*)d_in[12];
    const float* lin_w  = (const float*)d_in[13];
    const float* lin_b  = (const float*)d_in[14];
    const float* cls_w  = (const float*)d_in[15];
    const float* cls_b  = (const float*)d_in[16];
    float* out = (float*)d_out;

    int N = in_sizes[0] / FDIM;
    long long E = (long long)in_sizes[1] / 2;

    int nodeBlocks = (N + 7) / 8;
    int edgeBlocks = (int)((E + 255) / 256);
    int scanBlocks = (N + 1023) / 1024;
    int gemmBlocks = (N + 15) / 16;
    int zgrid = (N > GNUM * FDIM ? N : GNUM * FDIM);

    k_probe<<<1, 32>>>(ei);
    k_zero_pre<<<(zgrid + 255) / 256, 256>>>(N);
    k_prep<<<edgeBlocks, 256>>>(ei, E);
    k_scan1<<<scanBlocks, 1024>>>(N);
    k_scan2<<<1, 32>>>(scanBlocks, N);
    k_scan3<<<scanBlocks, 1024>>>(N);
    k_fill<<<edgeBlocks, 256>>>(E);

    // ---- layer 1 ----
    k_gemm<<<gemmBlocks, 128>>>(x, W1, as1, ad1, N);
    k_agg<<<nodeBlocks, 256>>>(b1, batch, N);
    // fused: layer-1 softmax/gate/pool + layer-2 GEMM
    k_ngp_gemm<<<gemmBlocks, 128>>>(batch, gate_w, gate_b, W2, as2, ad2, N);
    k_fin<<<(GNUM * FDIM + 255) / 256, 256>>>();

    // ---- layer 2 ----
    k_agg<<<nodeBlocks, 256>>>(b2, batch, N);
    k_ngp<<<nodeBlocks, 256>>>(batch, gate_w, gate_b, N);
    k_fin<<<(GNUM * FDIM + 255) / 256, 256>>>();

    k_head<<<GNUM, HID2>>>(lin_w, lin_b, cls_w, cls_b, out);
}

// round 7
// speedup vs baseline: 1.6138x; 1.0103x over previous
#include <cuda_runtime.h>
#include <cuda_fp16.h>
#include <cuda_fp8.h>
#include <cstdint>
#include <cstddef>

#define NMAX 50048
#define EMAX 1700000
#define FDIM 128
#define GNUM 64
#define HID2 64
#define OUTD 10

// ---------------- scratch ----------------
__device__ __align__(16) unsigned char  g_hw8 [NMAX * FDIM];  // layer-1 rows, e4m3
__device__ __align__(16) unsigned short g_hw16[NMAX * FDIM];  // layer-2 rows, fp16
__device__ __align__(16) float g_acc[NMAX * FDIM];
__device__ __align__(16) float g_als[NMAX * 4];
__device__ __align__(16) float g_ald[NMAX * 4];
__device__ __align__(16) float g_colsum[GNUM * FDIM];
__device__ __align__(16) float g_num[GNUM * FDIM];
__device__ __align__(16) float g_gatesum[GNUM];
__device__ __align__(16) float g_hg [GNUM * FDIM];
__device__ int g_src32[EMAX];
__device__ int g_dst32[EMAX];
__device__ int g_deg[NMAX];
__device__ int g_off[NMAX + 1];
__device__ int g_cur[NMAX];
__device__ int g_csr[EMAX];
__device__ int g_bsum[64];
__device__ int g_idx64;

__device__ __forceinline__ int load_idx(const void* p, long long i, int f64) {
    return f64 ? (int)((const long long*)p)[i] : ((const int*)p)[i];
}
__device__ __forceinline__ void red_add_v4(float* ptr, float a, float b, float c, float d) {
    asm volatile("red.global.add.v4.f32 [%0], {%1,%2,%3,%4};"
                 :: "l"(ptr), "f"(a), "f"(b), "f"(c), "f"(d) : "memory");
}
// row loaders: lane covers features [4*lane, 4*lane+4)
template<int BITS> __device__ __forceinline__ float4 ldrow(int n, int lane);
template<> __device__ __forceinline__ float4 ldrow<16>(int n, int lane) {
    uint2 raw = ((const uint2*)(g_hw16 + (size_t)n * 128))[lane];
    __half2 h01 = *reinterpret_cast<__half2*>(&raw.x);
    __half2 h23 = *reinterpret_cast<__half2*>(&raw.y);
    float2 f01 = __half22float2(h01);
    float2 f23 = __half22float2(h23);
    return make_float4(f01.x, f01.y, f23.x, f23.y);
}
template<> __device__ __forceinline__ float4 ldrow<8>(int n, int lane) {
    unsigned int raw = ((const unsigned int*)(g_hw8 + (size_t)n * 128))[lane];
    __nv_fp8x2_storage_t lo = (__nv_fp8x2_storage_t)(raw & 0xffffu);
    __nv_fp8x2_storage_t hi = (__nv_fp8x2_storage_t)(raw >> 16);
    __half2_raw h0 = __nv_cvt_fp8x2_to_halfraw2(lo, __NV_E4M3);
    __half2_raw h1 = __nv_cvt_fp8x2_to_halfraw2(hi, __NV_E4M3);
    float2 f0 = __half22float2(*reinterpret_cast<__half2*>(&h0));
    float2 f1 = __half22float2(*reinterpret_cast<__half2*>(&h1));
    return make_float4(f0.x, f0.y, f1.x, f1.y);
}

__global__ void k_probe(const void* ei) {
    if (threadIdx.x == 0) {
        const int* w = (const int*)ei;
        int f = 1;
        for (int i = 0; i < 64; i++) if (w[2 * i + 1] != 0) { f = 0; break; }
        g_idx64 = f;
    }
}

__global__ void k_zero_pre(int N) {
    int t = blockIdx.x * blockDim.x + threadIdx.x;
    if (t < N) g_deg[t] = 0;
    if (t < GNUM * FDIM) { g_colsum[t] = 0.f; g_num[t] = 0.f; g_hg[t] = 0.f; }
    if (t < GNUM) g_gatesum[t] = 0.f;
}

__global__ void k_prep(const void* __restrict__ ei, long long E) {
    long long t = (long long)blockIdx.x * blockDim.x + threadIdx.x;
    if (t >= E) return;
    int f64 = g_idx64;
    int s = load_idx(ei, t, f64);
    int d = load_idx(ei, E + t, f64);
    g_src32[t] = s;
    g_dst32[t] = d;
    atomicAdd(&g_deg[d], 1);
}

// ---- multi-block exclusive scan ----
__global__ void k_scan1(int N) {
    __shared__ int wsum[32];
    int b = blockIdx.x;
    int i = b * 1024 + threadIdx.x;
    int lane = threadIdx.x & 31, w = threadIdx.x >> 5;
    int v = (i < N) ? g_deg[i] : 0;
    int x = v;
#pragma unroll
    for (int off = 1; off < 32; off <<= 1) {
        int y = __shfl_up_sync(0xffffffffu, x, off);
        if (lane >= off) x += y;
    }
    if (lane == 31) wsum[w] = x;
    __syncthreads();
    if (w == 0) {
        int s = wsum[lane];
#pragma unroll
        for (int off = 1; off < 32; off <<= 1) {
            int y = __shfl_up_sync(0xffffffffu, s, off);
            if (lane >= off) s += y;
        }
        wsum[lane] = s;
    }
    __syncthreads();
    int excl = x - v + (w ? wsum[w - 1] : 0);
    if (i < N) g_off[i] = excl;
    if (threadIdx.x == 1023) g_bsum[b] = excl + v;
}

// scan3 now also does the block-sum prefix itself (scan2 merged away)
__global__ void k_scan3(int nb, int N) {
    __shared__ int s_off, s_tot;
    if (threadIdx.x < 32) {
        int lane = threadIdx.x;
        int v0 = (lane < nb) ? g_bsum[lane] : 0;
        int v1 = (lane + 32 < nb) ? g_bsum[lane + 32] : 0;
        int pre = 0, tot = 0;
        for (int j = 0; j < 64; j++) {
            int vj = __shfl_sync(0xffffffffu, (j < 32) ? v0 : v1, j & 31);
            if (j < (int)blockIdx.x) pre += vj;
            tot += vj;
        }
        if (lane == 0) { s_off = pre; s_tot = tot; }
    }
    __syncthreads();
    int i = blockIdx.x * 1024 + threadIdx.x;
    if (i < N) {
        int o = g_off[i] + s_off;
        g_off[i] = o;
        g_cur[i] = o;
    }
    if (blockIdx.x == 0 && threadIdx.x == 0) g_off[N] = s_tot;
}

__global__ void k_fill(long long E) {
    long long t = (long long)blockIdx.x * blockDim.x + threadIdx.x;
    if (t >= E) return;
    int s = g_src32[t];
    int d = g_dst32[t];
    int pos = atomicAdd(&g_cur[d], 1);
    g_csr[pos] = s;
}

// GEMM core on an smem tile; stores rows in fp8 (layer 1) or fp16 (layer 2).
template<int BITS>
__device__ __forceinline__ void gemm_tile(const float* sx, const float* __restrict__ W,
                                          const float* __restrict__ a_src,
                                          const float* __restrict__ a_dst,
                                          int row0, int N) {
    int col = threadIdx.x;
    unsigned long long acc2[16];
#pragma unroll
    for (int r = 0; r < 16; r++) acc2[r] = 0ull;
#pragma unroll 4
    for (int k = 0; k < 128; k += 4) {
        float w0 = W[(k + 0) * 128 + col];
        float w1 = W[(k + 1) * 128 + col];
        float w2 = W[(k + 2) * 128 + col];
        float w3 = W[(k + 3) * 128 + col];
        unsigned long long wp01, wp23;
        asm("mov.b64 %0,{%1,%2};" : "=l"(wp01) : "f"(w0), "f"(w1));
        asm("mov.b64 %0,{%1,%2};" : "=l"(wp23) : "f"(w2), "f"(w3));
#pragma unroll
        for (int r = 0; r < 16; r++) {
            ulonglong2 a = *(const ulonglong2*)&sx[r * 128 + k];
            asm("fma.rn.f32x2 %0,%1,%2,%0;" : "+l"(acc2[r]) : "l"(a.x), "l"(wp01));
            asm("fma.rn.f32x2 %0,%1,%2,%0;" : "+l"(acc2[r]) : "l"(a.y), "l"(wp23));
        }
    }
    float a_s = a_src[col];
    float a_d = a_dst[col];
    int wrp = threadIdx.x >> 5, lane = threadIdx.x & 31;
#pragma unroll
    for (int r = 0; r < 16; r++) {
        float lo, hi;
        asm("mov.b64 {%0,%1},%2;" : "=f"(lo), "=f"(hi) : "l"(acc2[r]));
        float acc = lo + hi;
        int row = row0 + r;
        float ps = acc * a_s;
        float pd = acc * a_d;
#pragma unroll
        for (int off = 16; off; off >>= 1) {
            ps += __shfl_xor_sync(0xffffffffu, ps, off);
            pd += __shfl_xor_sync(0xffffffffu, pd, off);
        }
        if (row < N) {
            if (BITS == 8) {
                g_hw8[(size_t)row * 128 + col] =
                    __nv_cvt_float_to_fp8(acc, __NV_SATFINITE, __NV_E4M3);
            } else {
                g_hw16[(size_t)row * 128 + col] = __half_as_ushort(__float2half_rn(acc));
            }
            if (lane == 0) {
                g_als[row * 4 + wrp] = ps;
                g_ald[row * 4 + wrp] = pd;
            }
        }
    }
}

// ---------------- layer-1 GEMM (input x) ----------------
__global__ void k_gemm(const float* __restrict__ A, const float* __restrict__ W,
                       const float* __restrict__ a_src, const float* __restrict__ a_dst, int N) {
    __shared__ __align__(16) float sx[16 * 128];
    int row0 = blockIdx.x * 16;
    float4* sx4 = (float4*)sx;
    const float4* A4 = (const float4*)A;
    for (int i = threadIdx.x; i < 512; i += 128) {
        int r = i >> 5;
        if (row0 + r < N) sx4[i] = A4[(size_t)(row0 + r) * 32 + (i & 31)];
        else sx4[i] = make_float4(0.f, 0.f, 0.f, 0.f);
    }
    __syncthreads();
    gemm_tile<8>(sx, W, a_src, a_dst, row0, N);
}

// ---------------- fused: layer-1 ngp + layer-2 GEMM ----------------
__global__ void k_ngp_gemm(const void* __restrict__ batch,
                           const float* __restrict__ gate_w, const float* __restrict__ gate_b,
                           const float* __restrict__ W,
                           const float* __restrict__ a_src, const float* __restrict__ a_dst,
                           int N) {
    __shared__ __align__(16) float sx[16 * 128];
    __shared__ float sge[16];
    __shared__ int sgid[16];
    __shared__ float spart[16][4];
    int row0 = blockIdx.x * 16;
    int tid = threadIdx.x;
    int wrp = tid >> 5, lane = tid & 31;
    int f64 = g_idx64;
    float4* sx4 = (float4*)sx;
    const float4* acc4 = (const float4*)g_acc;
    for (int i = tid; i < 512; i += 128) {
        int r = i >> 5, c = i & 31;
        int row = row0 + r;
        if (row < N) {
            int g = load_idx(batch, row, f64);
            if (c == 0) sgid[r] = g;
            float4 e = acc4[(size_t)row * 32 + c];
            float4 cs = ((const float4*)(g_colsum + g * 128))[c];
            sx4[i] = make_float4(__fdividef(e.x, cs.x), __fdividef(e.y, cs.y),
                                 __fdividef(e.z, cs.z), __fdividef(e.w, cs.w));
        } else {
            if (c == 0) sgid[r] = 0;
            sx4[i] = make_float4(0.f, 0.f, 0.f, 0.f);
        }
    }
    __syncthreads();
    float gwv = gate_w[tid];
#pragma unroll
    for (int r = 0; r < 16; r++) {
        float p = sx[r * 128 + tid] * gwv;
#pragma unroll
        for (int off = 16; off; off >>= 1) p += __shfl_xor_sync(0xffffffffu, p, off);
        if (lane == 0) spart[r][wrp] = p;
    }
    __syncthreads();
    if (tid < 16) {
        float p = spart[tid][0] + spart[tid][1] + spart[tid][2] + spart[tid][3] + gate_b[0];
        float ge = __expf(p);
        sge[tid] = ge;
        if (row0 + tid < N) atomicAdd(&g_gatesum[sgid[tid]], ge);
    }
    __syncthreads();
#pragma unroll
    for (int rr = 0; rr < 4; rr++) {
        int r = wrp + rr * 4;
        if (row0 + r < N) {
            float ge = sge[r];
            float4 hs = sx4[r * 32 + lane];
            red_add_v4(g_num + sgid[r] * 128 + lane * 4,
                       ge * hs.x, ge * hs.y, ge * hs.z, ge * hs.w);
        }
    }
    gemm_tile<16>(sx, W, a_src, a_dst, row0, N);
}

// ---------------- aggregation: warp per dst (CSR gather) ----------------
template<int BITS>
__global__ void k_agg(const float* __restrict__ bvec, const void* __restrict__ batch, int N) {
    int n = blockIdx.x * 8 + (threadIdx.x >> 5);
    int lane = threadIdx.x & 31;
    if (n >= N) return;
    const unsigned FULL = 0xffffffffu;
    int hf = lane >> 3;
    int hq = lane & 3;
    float ald_q = g_ald[n * 4 + hq];
    float lg = g_als[n * 4 + hq] + ald_q;
    lg = lg > 0.f ? lg : 0.2f * lg;
    float wq = __expf(lg);
    float ssum_q = wq;
    float wf = __shfl_sync(FULL, wq, hf);
    float4 v = ldrow<BITS>(n, lane);
    float4 acc = make_float4(wf * v.x, wf * v.y, wf * v.z, wf * v.w);

    int beg = g_off[n], end = g_off[n + 1];
    for (int j = beg; j < end; j += 8) {
        int rem = end - j;
        int et = lane >> 2;
        int s_e = 0; float wv = 0.f;
        if (et < rem) {
            s_e = g_csr[j + et];
            float l2 = g_als[s_e * 4 + hq] + ald_q;
            l2 = l2 > 0.f ? l2 : 0.2f * l2;
            wv = __expf(l2);
        }
        ssum_q += wv;
        int cnt = rem < 8 ? rem : 8;
#pragma unroll
        for (int t = 0; t < 8; t++) {
            if (t >= cnt) break;
            float w = __shfl_sync(FULL, wv, t * 4 + hf);
            int s = __shfl_sync(FULL, s_e, t * 4);
            float4 u = ldrow<BITS>(s, lane);
            acc.x += w * u.x; acc.y += w * u.y; acc.z += w * u.z; acc.w += w * u.w;
        }
    }
#pragma unroll
    for (int off = 4; off < 32; off <<= 1) ssum_q += __shfl_xor_sync(FULL, ssum_q, off);
    float inv = __fdividef(1.f, __shfl_sync(FULL, ssum_q, hf));

    float4 b = ((const float4*)bvec)[lane];
    float4 u;
    u.x = fmaxf(acc.x * inv + b.x, 0.f);
    u.y = fmaxf(acc.y * inv + b.y, 0.f);
    u.z = fmaxf(acc.z * inv + b.z, 0.f);
    u.w = fmaxf(acc.w * inv + b.w, 0.f);
    float4 ev = make_float4(__expf(u.x), __expf(u.y), __expf(u.z), __expf(u.w));
    ((float4*)(g_acc + (size_t)n * 128))[lane] = ev;
    int g = load_idx(batch, n, g_idx64);
    red_add_v4(g_colsum + g * 128 + lane * 4, ev.x, ev.y, ev.z, ev.w);
}

// ---------------- layer-2: softmax + gate + pool ----------------
__global__ void k_ngp(const void* __restrict__ batch, const float* __restrict__ gate_w,
                      const float* __restrict__ gate_b, int N) {
    int t = blockIdx.x * blockDim.x + threadIdx.x;
    int n = t >> 5, lane = t & 31;
    if (n >= N) return;
    const unsigned FULL = 0xffffffffu;
    int g = load_idx(batch, n, g_idx64);
    float4 e = ((const float4*)(g_acc + (size_t)n * 128))[lane];
    float4 c = ((const float4*)(g_colsum + g * 128))[lane];
    float4 hs = make_float4(__fdividef(e.x, c.x), __fdividef(e.y, c.y),
                            __fdividef(e.z, c.z), __fdividef(e.w, c.w));
    float4 gw = ((const float4*)gate_w)[lane];
    float p = hs.x * gw.x + hs.y * gw.y + hs.z * gw.z + hs.w * gw.w;
#pragma unroll
    for (int off = 16; off; off >>= 1) p += __shfl_xor_sync(FULL, p, off);
    float ge = __expf(p + gate_b[0]);
    red_add_v4(g_num + g * 128 + lane * 4, ge * hs.x, ge * hs.y, ge * hs.z, ge * hs.w);
    if (lane == 0) atomicAdd(&g_gatesum[g], ge);
}

__global__ void k_fin() {
    int t = blockIdx.x * blockDim.x + threadIdx.x;
    if (t < GNUM * FDIM) {
        g_hg[t] += g_num[t] * __fdividef(1.f, g_gatesum[t >> 7]);
        g_num[t] = 0.f;
        g_colsum[t] = 0.f;
    }
    if (t < GNUM) g_gatesum[t] = 0.f;
}

// ---------------- MLP head ----------------
__global__ void k_head(const float* __restrict__ lin_w, const float* __restrict__ lin_b,
                       const float* __restrict__ cls_w, const float* __restrict__ cls_b,
                       float* __restrict__ out) {
    int g = blockIdx.x;
    int j = threadIdx.x;
    __shared__ float sh[HID2];
    float a = lin_b[j];
#pragma unroll 4
    for (int k = 0; k < 128; k++) a += g_hg[g * 128 + k] * lin_w[k * HID2 + j];
    sh[j] = fmaxf(a, 0.f);
    __syncthreads();
    if (j < OUTD) {
        float o = cls_b[j];
#pragma unroll
        for (int k = 0; k < HID2; k++) o += sh[k] * cls_w[k * OUTD + j];
        out[g * OUTD + j] = o;
    }
}

// ---------------- launch ----------------
extern "C" void kernel_launch(void* const* d_in, const int* in_sizes, int n_in,
                              void* d_out, int out_size) {
    const float* x      = (const float*)d_in[0];
    const void*  ei     = d_in[1];
    const void*  batch  = d_in[2];
    const float* W1     = (const float*)d_in[3];
    const float* as1    = (const float*)d_in[4];
    const float* ad1    = (const float*)d_in[5];
    const float* b1     = (const float*)d_in[6];
    const float* W2     = (const float*)d_in[7];
    const float* as2    = (const float*)d_in[8];
    const float* ad2    = (const float*)d_in[9];
    const float* b2     = (const float*)d_in[10];
    const float* gate_w = (const float*)d_in[11];
    const float* gate_b = (const float*)d_in[12];
    const float* lin_w  = (const float*)d_in[13];
    const float* lin_b  = (const float*)d_in[14];
    const float* cls_w  = (const float*)d_in[15];
    const float* cls_b  = (const float*)d_in[16];
    float* out = (float*)d_out;

    int N = in_sizes[0] / FDIM;
    long long E = (long long)in_sizes[1] / 2;

    int nodeBlocks = (N + 7) / 8;
    int edgeBlocks = (int)((E + 255) / 256);
    int scanBlocks = (N + 1023) / 1024;
    int gemmBlocks = (N + 15) / 16;
    int zgrid = (N > GNUM * FDIM ? N : GNUM * FDIM);

    k_probe<<<1, 32>>>(ei);
    k_zero_pre<<<(zgrid + 255) / 256, 256>>>(N);
    k_prep<<<edgeBlocks, 256>>>(ei, E);
    k_scan1<<<scanBlocks, 1024>>>(N);
    k_scan3<<<scanBlocks, 1024>>>(scanBlocks, N);
    k_fill<<<edgeBlocks, 256>>>(E);

    // ---- layer 1 (fp8 rows) ----
    k_gemm<<<gemmBlocks, 128>>>(x, W1, as1, ad1, N);
    k_agg<8><<<nodeBlocks, 256>>>(b1, batch, N);
    k_ngp_gemm<<<gemmBlocks, 128>>>(batch, gate_w, gate_b, W2, as2, ad2, N);
    k_fin<<<(GNUM * FDIM + 255) / 256, 256>>>();

    // ---- layer 2 (fp16 rows) ----
    k_agg<16><<<nodeBlocks, 256>>>(b2, batch, N);
    k_ngp<<<nodeBlocks, 256>>>(batch, gate_w, gate_b, N);
    k_fin<<<(GNUM * FDIM + 255) / 256, 256>>>();

    k_head<<<GNUM, HID2>>>(lin_w, lin_b, cls_w, cls_b, out);
}

// round 8
// speedup vs baseline: 1.6386x; 1.0154x over previous
#include <cuda_runtime.h>
#include <cuda_fp16.h>
#include <cuda_fp8.h>
#include <cstdint>
#include <cstddef>

#define NMAX 50048
#define EMAX 1700000
#define FDIM 128
#define GNUM 64
#define HID2 64
#define OUTD 10

// ---------------- scratch ----------------
__device__ __align__(16) unsigned char  g_hw8 [NMAX * FDIM];  // h rows, e4m3 (scaled)
__device__ __align__(16) float g_acc[NMAX * FDIM];
__device__ __align__(16) float g_als[NMAX * 4];
__device__ __align__(16) float g_ald[NMAX * 4];
__device__ __align__(16) float g_colsum[GNUM * FDIM];
__device__ __align__(16) float g_num[GNUM * FDIM];
__device__ __align__(16) float g_gatesum[GNUM];
__device__ __align__(16) float g_hg [GNUM * FDIM];
__device__ int g_src32[EMAX];
__device__ int g_dst32[EMAX];
__device__ int g_deg[NMAX];
__device__ int g_off[NMAX + 1];
__device__ int g_cur[NMAX];
__device__ int g_csr[EMAX];
__device__ int g_bsum[64];
__device__ int g_idx64;

__device__ __forceinline__ int load_idx(const void* p, long long i, int f64) {
    return f64 ? (int)((const long long*)p)[i] : ((const int*)p)[i];
}
__device__ __forceinline__ void red_add_v4(float* ptr, float a, float b, float c, float d) {
    asm volatile("red.global.add.v4.f32 [%0], {%1,%2,%3,%4};"
                 :: "l"(ptr), "f"(a), "f"(b), "f"(c), "f"(d) : "memory");
}
// fp8 row loader: lane covers features [4*lane, 4*lane+4)
__device__ __forceinline__ float4 ldrow8(int n, int lane) {
    unsigned int raw = ((const unsigned int*)(g_hw8 + (size_t)n * 128))[lane];
    __nv_fp8x2_storage_t lo = (__nv_fp8x2_storage_t)(raw & 0xffffu);
    __nv_fp8x2_storage_t hi = (__nv_fp8x2_storage_t)(raw >> 16);
    __half2_raw h0 = __nv_cvt_fp8x2_to_halfraw2(lo, __NV_E4M3);
    __half2_raw h1 = __nv_cvt_fp8x2_to_halfraw2(hi, __NV_E4M3);
    float2 f0 = __half22float2(*reinterpret_cast<__half2*>(&h0));
    float2 f1 = __half22float2(*reinterpret_cast<__half2*>(&h1));
    return make_float4(f0.x, f0.y, f1.x, f1.y);
}

__global__ void k_probe(const void* ei) {
    if (threadIdx.x == 0) {
        const int* w = (const int*)ei;
        int f = 1;
        for (int i = 0; i < 64; i++) if (w[2 * i + 1] != 0) { f = 0; break; }
        g_idx64 = f;
    }
}

__global__ void k_zero_pre(int N) {
    int t = blockIdx.x * blockDim.x + threadIdx.x;
    if (t < N) g_deg[t] = 0;
    if (t < GNUM * FDIM) { g_colsum[t] = 0.f; g_num[t] = 0.f; g_hg[t] = 0.f; }
    if (t < GNUM) g_gatesum[t] = 0.f;
}

__global__ void k_prep(const void* __restrict__ ei, long long E) {
    long long t = (long long)blockIdx.x * blockDim.x + threadIdx.x;
    if (t >= E) return;
    int f64 = g_idx64;
    int s = load_idx(ei, t, f64);
    int d = load_idx(ei, E + t, f64);
    g_src32[t] = s;
    g_dst32[t] = d;
    atomicAdd(&g_deg[d], 1);
}

// ---- multi-block exclusive scan ----
__global__ void k_scan1(int N) {
    __shared__ int wsum[32];
    int b = blockIdx.x;
    int i = b * 1024 + threadIdx.x;
    int lane = threadIdx.x & 31, w = threadIdx.x >> 5;
    int v = (i < N) ? g_deg[i] : 0;
    int x = v;
#pragma unroll
    for (int off = 1; off < 32; off <<= 1) {
        int y = __shfl_up_sync(0xffffffffu, x, off);
        if (lane >= off) x += y;
    }
    if (lane == 31) wsum[w] = x;
    __syncthreads();
    if (w == 0) {
        int s = wsum[lane];
#pragma unroll
        for (int off = 1; off < 32; off <<= 1) {
            int y = __shfl_up_sync(0xffffffffu, s, off);
            if (lane >= off) s += y;
        }
        wsum[lane] = s;
    }
    __syncthreads();
    int excl = x - v + (w ? wsum[w - 1] : 0);
    if (i < N) g_off[i] = excl;
    if (threadIdx.x == 1023) g_bsum[b] = excl + v;
}

__global__ void k_scan3(int nb, int N) {
    __shared__ int s_off, s_tot;
    if (threadIdx.x < 32) {
        int lane = threadIdx.x;
        int v0 = (lane < nb) ? g_bsum[lane] : 0;
        int v1 = (lane + 32 < nb) ? g_bsum[lane + 32] : 0;
        int pre = 0, tot = 0;
        for (int j = 0; j < 64; j++) {
            int vj = __shfl_sync(0xffffffffu, (j < 32) ? v0 : v1, j & 31);
            if (j < (int)blockIdx.x) pre += vj;
            tot += vj;
        }
        if (lane == 0) { s_off = pre; s_tot = tot; }
    }
    __syncthreads();
    int i = blockIdx.x * 1024 + threadIdx.x;
    if (i < N) {
        int o = g_off[i] + s_off;
        g_off[i] = o;
        g_cur[i] = o;
    }
    if (blockIdx.x == 0 && threadIdx.x == 0) g_off[N] = s_tot;
}

__global__ void k_fill(long long E) {
    long long t = (long long)blockIdx.x * blockDim.x + threadIdx.x;
    if (t >= E) return;
    int s = g_src32[t];
    int d = g_dst32[t];
    int pos = atomicAdd(&g_cur[d], 1);
    g_csr[pos] = s;
}

// GEMM core on an smem tile; stores rows as fp8(acc*scale) + als/ald (fp32).
__device__ __forceinline__ void gemm_tile(const float* sx, const float* __restrict__ W,
                                          const float* __restrict__ a_src,
                                          const float* __restrict__ a_dst,
                                          int row0, int N, float scale) {
    int col = threadIdx.x;
    unsigned long long acc2[16];
#pragma unroll
    for (int r = 0; r < 16; r++) acc2[r] = 0ull;
#pragma unroll 4
    for (int k = 0; k < 128; k += 4) {
        float w0 = W[(k + 0) * 128 + col];
        float w1 = W[(k + 1) * 128 + col];
        float w2 = W[(k + 2) * 128 + col];
        float w3 = W[(k + 3) * 128 + col];
        unsigned long long wp01, wp23;
        asm("mov.b64 %0,{%1,%2};" : "=l"(wp01) : "f"(w0), "f"(w1));
        asm("mov.b64 %0,{%1,%2};" : "=l"(wp23) : "f"(w2), "f"(w3));
#pragma unroll
        for (int r = 0; r < 16; r++) {
            ulonglong2 a = *(const ulonglong2*)&sx[r * 128 + k];
            asm("fma.rn.f32x2 %0,%1,%2,%0;" : "+l"(acc2[r]) : "l"(a.x), "l"(wp01));
            asm("fma.rn.f32x2 %0,%1,%2,%0;" : "+l"(acc2[r]) : "l"(a.y), "l"(wp23));
        }
    }
    float a_s = a_src[col];
    float a_d = a_dst[col];
    int wrp = threadIdx.x >> 5, lane = threadIdx.x & 31;
#pragma unroll
    for (int r = 0; r < 16; r++) {
        float lo, hi;
        asm("mov.b64 {%0,%1},%2;" : "=f"(lo), "=f"(hi) : "l"(acc2[r]));
        float acc = lo + hi;
        int row = row0 + r;
        float ps = acc * a_s;
        float pd = acc * a_d;
#pragma unroll
        for (int off = 16; off; off >>= 1) {
            ps += __shfl_xor_sync(0xffffffffu, ps, off);
            pd += __shfl_xor_sync(0xffffffffu, pd, off);
        }
        if (row < N) {
            g_hw8[(size_t)row * 128 + col] =
                __nv_cvt_float_to_fp8(acc * scale, __NV_SATFINITE, __NV_E4M3);
            if (lane == 0) {
                g_als[row * 4 + wrp] = ps;
                g_ald[row * 4 + wrp] = pd;
            }
        }
    }
}

// ---------------- layer-1 GEMM (input x) ----------------
__global__ void k_gemm(const float* __restrict__ A, const float* __restrict__ W,
                       const float* __restrict__ a_src, const float* __restrict__ a_dst,
                       int N, float scale) {
    __shared__ __align__(16) float sx[16 * 128];
    int row0 = blockIdx.x * 16;
    float4* sx4 = (float4*)sx;
    const float4* A4 = (const float4*)A;
    for (int i = threadIdx.x; i < 512; i += 128) {
        int r = i >> 5;
        if (row0 + r < N) sx4[i] = A4[(size_t)(row0 + r) * 32 + (i & 31)];
        else sx4[i] = make_float4(0.f, 0.f, 0.f, 0.f);
    }
    __syncthreads();
    gemm_tile(sx, W, a_src, a_dst, row0, N, scale);
}

// ---------------- fused: layer-1 ngp + layer-2 GEMM ----------------
__global__ void k_ngp_gemm(const void* __restrict__ batch,
                           const float* __restrict__ gate_w, const float* __restrict__ gate_b,
                           const float* __restrict__ W,
                           const float* __restrict__ a_src, const float* __restrict__ a_dst,
                           int N, float scale) {
    __shared__ __align__(16) float sx[16 * 128];
    __shared__ float sge[16];
    __shared__ int sgid[16];
    __shared__ float spart[16][4];
    int row0 = blockIdx.x * 16;
    int tid = threadIdx.x;
    int wrp = tid >> 5, lane = tid & 31;
    int f64 = g_idx64;
    float4* sx4 = (float4*)sx;
    const float4* acc4 = (const float4*)g_acc;
    for (int i = tid; i < 512; i += 128) {
        int r = i >> 5, c = i & 31;
        int row = row0 + r;
        if (row < N) {
            int g = load_idx(batch, row, f64);
            if (c == 0) sgid[r] = g;
            float4 e = acc4[(size_t)row * 32 + c];
            float4 cs = ((const float4*)(g_colsum + g * 128))[c];
            sx4[i] = make_float4(__fdividef(e.x, cs.x), __fdividef(e.y, cs.y),
                                 __fdividef(e.z, cs.z), __fdividef(e.w, cs.w));
        } else {
            if (c == 0) sgid[r] = 0;
            sx4[i] = make_float4(0.f, 0.f, 0.f, 0.f);
        }
    }
    __syncthreads();
    float gwv = gate_w[tid];
#pragma unroll
    for (int r = 0; r < 16; r++) {
        float p = sx[r * 128 + tid] * gwv;
#pragma unroll
        for (int off = 16; off; off >>= 1) p += __shfl_xor_sync(0xffffffffu, p, off);
        if (lane == 0) spart[r][wrp] = p;
    }
    __syncthreads();
    if (tid < 16) {
        float p = spart[tid][0] + spart[tid][1] + spart[tid][2] + spart[tid][3] + gate_b[0];
        float ge = __expf(p);
        sge[tid] = ge;
        if (row0 + tid < N) atomicAdd(&g_gatesum[sgid[tid]], ge);
    }
    __syncthreads();
#pragma unroll
    for (int rr = 0; rr < 4; rr++) {
        int r = wrp + rr * 4;
        if (row0 + r < N) {
            float ge = sge[r];
            float4 hs = sx4[r * 32 + lane];
            red_add_v4(g_num + sgid[r] * 128 + lane * 4,
                       ge * hs.x, ge * hs.y, ge * hs.z, ge * hs.w);
        }
    }
    gemm_tile(sx, W, a_src, a_dst, row0, N, scale);
}

// ---------------- aggregation: warp per dst (CSR gather, fp8 rows) ----------
__global__ void k_agg(const float* __restrict__ bvec, const void* __restrict__ batch,
                      int N, float invscale) {
    int n = blockIdx.x * 8 + (threadIdx.x >> 5);
    int lane = threadIdx.x & 31;
    if (n >= N) return;
    const unsigned FULL = 0xffffffffu;
    int hf = lane >> 3;
    int hq = lane & 3;
    float ald_q = g_ald[n * 4 + hq];
    float lg = g_als[n * 4 + hq] + ald_q;
    lg = lg > 0.f ? lg : 0.2f * lg;
    float wq = __expf(lg);
    float ssum_q = wq;
    float wf = __shfl_sync(FULL, wq, hf);
    float4 v = ldrow8(n, lane);
    float4 acc = make_float4(wf * v.x, wf * v.y, wf * v.z, wf * v.w);

    int beg = g_off[n], end = g_off[n + 1];
    for (int j = beg; j < end; j += 8) {
        int rem = end - j;
        int et = lane >> 2;
        int s_e = 0; float wv = 0.f;
        if (et < rem) {
            s_e = g_csr[j + et];
            float l2 = g_als[s_e * 4 + hq] + ald_q;
            l2 = l2 > 0.f ? l2 : 0.2f * l2;
            wv = __expf(l2);
        }
        ssum_q += wv;
        // unconditional 8-wide gather: tail lanes carry w=0, s=0 (row 0 is valid)
#pragma unroll
        for (int t = 0; t < 8; t++) {
            float w = __shfl_sync(FULL, wv, t * 4 + hf);
            int s = __shfl_sync(FULL, s_e, t * 4);
            float4 u = ldrow8(s, lane);
            acc.x += w * u.x; acc.y += w * u.y; acc.z += w * u.z; acc.w += w * u.w;
        }
    }
#pragma unroll
    for (int off = 4; off < 32; off <<= 1) ssum_q += __shfl_xor_sync(FULL, ssum_q, off);
    float inv = __fdividef(invscale, __shfl_sync(FULL, ssum_q, hf));

    float4 b = ((const float4*)bvec)[lane];
    float4 u;
    u.x = fmaxf(acc.x * inv + b.x, 0.f);
    u.y = fmaxf(acc.y * inv + b.y, 0.f);
    u.z = fmaxf(acc.z * inv + b.z, 0.f);
    u.w = fmaxf(acc.w * inv + b.w, 0.f);
    float4 ev = make_float4(__expf(u.x), __expf(u.y), __expf(u.z), __expf(u.w));
    ((float4*)(g_acc + (size_t)n * 128))[lane] = ev;
    int g = load_idx(batch, n, g_idx64);
    red_add_v4(g_colsum + g * 128 + lane * 4, ev.x, ev.y, ev.z, ev.w);
}

// ---------------- layer-2: softmax + gate + pool ----------------
__global__ void k_ngp(const void* __restrict__ batch, const float* __restrict__ gate_w,
                      const float* __restrict__ gate_b, int N) {
    int t = blockIdx.x * blockDim.x + threadIdx.x;
    int n = t >> 5, lane = t & 31;
    if (n >= N) return;
    const unsigned FULL = 0xffffffffu;
    int g = load_idx(batch, n, g_idx64);
    float4 e = ((const float4*)(g_acc + (size_t)n * 128))[lane];
    float4 c = ((const float4*)(g_colsum + g * 128))[lane];
    float4 hs = make_float4(__fdividef(e.x, c.x), __fdividef(e.y, c.y),
                            __fdividef(e.z, c.z), __fdividef(e.w, c.w));
    float4 gw = ((const float4*)gate_w)[lane];
    float p = hs.x * gw.x + hs.y * gw.y + hs.z * gw.z + hs.w * gw.w;
#pragma unroll
    for (int off = 16; off; off >>= 1) p += __shfl_xor_sync(FULL, p, off);
    float ge = __expf(p + gate_b[0]);
    red_add_v4(g_num + g * 128 + lane * 4, ge * hs.x, ge * hs.y, ge * hs.z, ge * hs.w);
    if (lane == 0) atomicAdd(&g_gatesum[g], ge);
}

__global__ void k_fin() {
    int t = blockIdx.x * blockDim.x + threadIdx.x;
    if (t < GNUM * FDIM) {
        g_hg[t] += g_num[t] * __fdividef(1.f, g_gatesum[t >> 7]);
        g_num[t] = 0.f;
        g_colsum[t] = 0.f;
    }
    if (t < GNUM) g_gatesum[t] = 0.f;
}

// ---------------- MLP head ----------------
__global__ void k_head(const float* __restrict__ lin_w, const float* __restrict__ lin_b,
                       const float* __restrict__ cls_w, const float* __restrict__ cls_b,
                       float* __restrict__ out) {
    int g = blockIdx.x;
    int j = threadIdx.x;
    __shared__ float sh[HID2];
    float a = lin_b[j];
#pragma unroll 4
    for (int k = 0; k < 128; k++) a += g_hg[g * 128 + k] * lin_w[k * HID2 + j];
    sh[j] = fmaxf(a, 0.f);
    __syncthreads();
    if (j < OUTD) {
        float o = cls_b[j];
#pragma unroll
        for (int k = 0; k < HID2; k++) o += sh[k] * cls_w[k * OUTD + j];
        out[g * OUTD + j] = o;
    }
}

// ---------------- launch ----------------
extern "C" void kernel_launch(void* const* d_in, const int* in_sizes, int n_in,
                              void* d_out, int out_size) {
    const float* x      = (const float*)d_in[0];
    const void*  ei     = d_in[1];
    const void*  batch  = d_in[2];
    const float* W1     = (const float*)d_in[3];
    const float* as1    = (const float*)d_in[4];
    const float* ad1    = (const float*)d_in[5];
    const float* b1     = (const float*)d_in[6];
    const float* W2     = (const float*)d_in[7];
    const float* as2    = (const float*)d_in[8];
    const float* ad2    = (const float*)d_in[9];
    const float* b2     = (const float*)d_in[10];
    const float* gate_w = (const float*)d_in[11];
    const float* gate_b = (const float*)d_in[12];
    const float* lin_w  = (const float*)d_in[13];
    const float* lin_b  = (const float*)d_in[14];
    const float* cls_w  = (const float*)d_in[15];
    const float* cls_b  = (const float*)d_in[16];
    float* out = (float*)d_out;

    int N = in_sizes[0] / FDIM;
    long long E = (long long)in_sizes[1] / 2;

    int nodeBlocks = (N + 7) / 8;
    int edgeBlocks = (int)((E + 255) / 256);
    int scanBlocks = (N + 1023) / 1024;
    int gemmBlocks = (N + 15) / 16;
    int zgrid = (N > GNUM * FDIM ? N : GNUM * FDIM);

    k_probe<<<1, 32>>>(ei);
    k_zero_pre<<<(zgrid + 255) / 256, 256>>>(N);
    k_prep<<<edgeBlocks, 256>>>(ei, E);
    k_scan1<<<scanBlocks, 1024>>>(N);
    k_scan3<<<scanBlocks, 1024>>>(scanBlocks, N);
    k_fill<<<edgeBlocks, 256>>>(E);

    // ---- layer 1 (fp8 rows, scale 1) ----
    k_gemm<<<gemmBlocks, 128>>>(x, W1, as1, ad1, N, 1.0f);
    k_agg<<<nodeBlocks, 256>>>(b1, batch, N, 1.0f);
    // ---- layer-1 pool + layer-2 GEMM (fp8 rows, scale 64) ----
    k_ngp_gemm<<<gemmBlocks, 128>>>(batch, gate_w, gate_b, W2, as2, ad2, N, 64.0f);
    k_fin<<<(GNUM * FDIM + 255) / 256, 256>>>();

    // ---- layer 2 ----
    k_agg<<<nodeBlocks, 256>>>(b2, batch, N, 1.0f / 64.0f);
    k_ngp<<<nodeBlocks, 256>>>(batch, gate_w, gate_b, N);
    k_fin<<<(GNUM * FDIM + 255) / 256, 256>>>();

    k_head<<<GNUM, HID2>>>(lin_w, lin_b, cls_w, cls_b, out);
}